// round 1
// baseline (speedup 1.0000x reference)
#include <cuda_runtime.h>
#include <math.h>
#include <float.h>

// Problem constants
#define NS 2048        // n
#define BB 4096        // 2n
#define DD 512         // feature dim
#define CC 128         // num classes / prob dim

// Scratch (allocation-free rule: __device__ globals)
__device__ float g_d2[(size_t)BB * BB];   // 64 MB pairwise squared distances
__device__ float g_sq[BB];                // row squared norms
__device__ float g_part[BB];              // per-row partial sums

// ---------------------------------------------------------------------------
// Kernel 1: row squared norms of feats = concat(z_i, z_j). One warp per row.
// ---------------------------------------------------------------------------
__global__ void sq_kernel(const float* __restrict__ zi, const float* __restrict__ zj) {
    int w = (blockIdx.x * blockDim.x + threadIdx.x) >> 5;
    int lane = threadIdx.x & 31;
    if (w >= BB) return;
    const float* p = (w < NS) ? zi + (size_t)w * DD : zj + (size_t)(w - NS) * DD;
    const float4* p4 = (const float4*)p;
    float s = 0.f;
    #pragma unroll
    for (int k = lane; k < DD / 4; k += 32) {
        float4 v = p4[k];
        s += v.x * v.x + v.y * v.y + v.z * v.z + v.w * v.w;
    }
    #pragma unroll
    for (int o = 16; o; o >>= 1) s += __shfl_xor_sync(0xffffffffu, s, o);
    if (lane == 0) g_sq[w] = s;
}

// ---------------------------------------------------------------------------
// Kernel 2: symmetric fp32 GEMM (F F^T), fused into d2 = |fi|^2+|fj|^2-2<fi,fj>.
// 128x128 block tile, BK=16, 256 threads, 8x8 per thread, double-buffered smem.
// Only upper-triangular tiles computed (528 of 1024); results mirrored.
// ---------------------------------------------------------------------------
__global__ void __launch_bounds__(256, 2)
gemm_d2_kernel(const float* __restrict__ zi, const float* __restrict__ zj) {
    // map linear block id -> (bi, bj) with bj >= bi on a 32x32 tile grid
    int t = blockIdx.x;
    int bi = 0;
    while (t >= 32 - bi) { t -= 32 - bi; ++bi; }
    int bj = bi + t;
    const int m0 = bi << 7, n0 = bj << 7;

    // tiles never straddle the z_i/z_j boundary (2048 % 128 == 0)
    const float* Ab = (m0 < NS) ? zi + (size_t)m0 * DD : zj + (size_t)(m0 - NS) * DD;
    const float* Bb = (n0 < NS) ? zi + (size_t)n0 * DD : zj + (size_t)(n0 - NS) * DD;

    __shared__ float As[2][16][132];   // [k][m], padded (132*4B = 33*16B keeps f4 align)
    __shared__ float Bs[2][16][132];   // [k][n]

    const int tid = threadIdx.x;
    const int ty = tid >> 4, tx = tid & 15;
    const int r0 = tid >> 2;            // 0..63
    const int c4 = (tid & 3) * 4;       // 0,4,8,12

    float acc[8][8];
    #pragma unroll
    for (int i = 0; i < 8; i++)
        #pragma unroll
        for (int j = 0; j < 8; j++) acc[i][j] = 0.f;

    float4 pa0, pa1, pb0, pb1;
    auto fetch = [&](int kt) {
        const int kc = kt * 16 + c4;
        pa0 = *(const float4*)(Ab + (size_t)r0 * DD + kc);
        pa1 = *(const float4*)(Ab + (size_t)(r0 + 64) * DD + kc);
        pb0 = *(const float4*)(Bb + (size_t)r0 * DD + kc);
        pb1 = *(const float4*)(Bb + (size_t)(r0 + 64) * DD + kc);
    };
    auto stash = [&](int buf) {
        As[buf][c4 + 0][r0] = pa0.x; As[buf][c4 + 1][r0] = pa0.y;
        As[buf][c4 + 2][r0] = pa0.z; As[buf][c4 + 3][r0] = pa0.w;
        As[buf][c4 + 0][r0 + 64] = pa1.x; As[buf][c4 + 1][r0 + 64] = pa1.y;
        As[buf][c4 + 2][r0 + 64] = pa1.z; As[buf][c4 + 3][r0 + 64] = pa1.w;
        Bs[buf][c4 + 0][r0] = pb0.x; Bs[buf][c4 + 1][r0] = pb0.y;
        Bs[buf][c4 + 2][r0] = pb0.z; Bs[buf][c4 + 3][r0] = pb0.w;
        Bs[buf][c4 + 0][r0 + 64] = pb1.x; Bs[buf][c4 + 1][r0 + 64] = pb1.y;
        Bs[buf][c4 + 2][r0 + 64] = pb1.z; Bs[buf][c4 + 3][r0 + 64] = pb1.w;
    };

    fetch(0); stash(0); __syncthreads();
    int buf = 0;
    const int NT = DD / 16;   // 32 K-tiles
    for (int kt = 0; kt < NT; ++kt) {
        if (kt + 1 < NT) fetch(kt + 1);
        #pragma unroll
        for (int k = 0; k < 16; ++k) {
            float4 a0 = *(const float4*)&As[buf][k][ty * 8];
            float4 a1 = *(const float4*)&As[buf][k][ty * 8 + 4];
            float4 b0 = *(const float4*)&Bs[buf][k][tx * 8];
            float4 b1 = *(const float4*)&Bs[buf][k][tx * 8 + 4];
            float a[8] = {a0.x, a0.y, a0.z, a0.w, a1.x, a1.y, a1.z, a1.w};
            float b[8] = {b0.x, b0.y, b0.z, b0.w, b1.x, b1.y, b1.z, b1.w};
            #pragma unroll
            for (int i = 0; i < 8; i++)
                #pragma unroll
                for (int j = 0; j < 8; j++) acc[i][j] += a[i] * b[j];
        }
        if (kt + 1 < NT) {
            __syncthreads();      // everyone done reading buf^1 from prev iter
            stash(buf ^ 1);
            __syncthreads();      // stores visible
        }
        buf ^= 1;
    }

    float sm[8], sn[8];
    #pragma unroll
    for (int q = 0; q < 8; q++) {
        sm[q] = g_sq[m0 + ty * 8 + q];
        sn[q] = g_sq[n0 + tx * 8 + q];
    }
    #pragma unroll
    for (int ii = 0; ii < 8; ii++) {
        int gm = m0 + ty * 8 + ii;
        float d[8];
        #pragma unroll
        for (int jj = 0; jj < 8; jj++) d[jj] = sm[ii] + sn[jj] - 2.f * acc[ii][jj];
        // main store (coalesced float4)
        float4* dst = (float4*)&g_d2[(size_t)gm * BB + n0 + tx * 8];
        dst[0] = make_float4(d[0], d[1], d[2], d[3]);
        dst[1] = make_float4(d[4], d[5], d[6], d[7]);
        // mirror store (scalar; diagonal-block overlap writes identical bits)
        #pragma unroll
        for (int jj = 0; jj < 8; jj++) {
            int gn = n0 + tx * 8 + jj;
            g_d2[(size_t)gn * BB + gm] = d[jj];
        }
    }
}

// ---------------------------------------------------------------------------
// Kernel 3: per-row top-10 nearest (non-self) selection + masked weighted
// prob-dot accumulation. One warp per row.
// ---------------------------------------------------------------------------
__global__ void select_loss_kernel(const float* __restrict__ zip,
                                   const float* __restrict__ zjp,
                                   const int* __restrict__ label) {
    int w = (blockIdx.x * blockDim.x + threadIdx.x) >> 5;
    int lane = threadIdx.x & 31;
    if (w >= BB) return;
    const int i = w;
    const float* drow = g_d2 + (size_t)i * BB;

    // per-lane sorted top-10 smallest (ascending)
    float v[10]; int c[10];
    #pragma unroll
    for (int q = 0; q < 10; q++) { v[q] = FLT_MAX; c[q] = -1; }
    for (int j = lane; j < BB; j += 32) {
        float d = drow[j];
        if (j == i) continue;
        if (d < v[9]) {
            v[9] = d; c[9] = j;
            #pragma unroll
            for (int q = 9; q >= 1; q--) {
                if (v[q] < v[q - 1]) {
                    float tv = v[q]; v[q] = v[q - 1]; v[q - 1] = tv;
                    int tc = c[q]; c[q] = c[q - 1]; c[q - 1] = tc;
                }
            }
        }
    }

    // warp merge: 10 rounds of argmin-extract (heads stay at index 0)
    float rv[10]; int rc[10];
    #pragma unroll
    for (int r = 0; r < 10; r++) {
        float mv = v[0]; int mc = c[0];
        #pragma unroll
        for (int o = 16; o; o >>= 1) {
            float ov = __shfl_down_sync(0xffffffffu, mv, o);
            int oc = __shfl_down_sync(0xffffffffu, mc, o);
            if (ov < mv || (ov == mv && (unsigned)oc < (unsigned)mc)) { mv = ov; mc = oc; }
        }
        mv = __shfl_sync(0xffffffffu, mv, 0);
        mc = __shfl_sync(0xffffffffu, mc, 0);
        rv[r] = mv; rc[r] = mc;
        if (c[0] == mc && mc >= 0) {       // winner lane pops its head
            #pragma unroll
            for (int q = 0; q < 9; q++) { v[q] = v[q + 1]; c[q] = c[q + 1]; }
            v[9] = FLT_MAX; c[9] = -1;
        }
    }

    // radius = nearest non-self distance; w_k = 1 - clip((pd-r)/r, 0, 1)
    float radius = sqrtf(fmaxf(rv[0], 0.f));
    const float* prow = (i < NS) ? zip + (size_t)i * CC : zjp + (size_t)(i - NS) * CC;
    float4 myp = ((const float4*)prow)[lane];   // CC=128 -> 32 lanes x float4
    const int im = i & (NS - 1);
    const int li = label[im];
    float rowsum = 0.f;
    #pragma unroll
    for (int r = 0; r < 10; r++) {
        int j = rc[r];
        int jm = j & (NS - 1);
        if (li == label[jm] && li != -1 && im != jm) {
            const float* pr = (j < NS) ? zip + (size_t)j * CC : zjp + (size_t)(j - NS) * CC;
            float4 q4 = ((const float4*)pr)[lane];
            float part = myp.x * q4.x + myp.y * q4.y + myp.z * q4.z + myp.w * q4.w;
            #pragma unroll
            for (int o = 16; o; o >>= 1) part += __shfl_xor_sync(0xffffffffu, part, o);
            float pd = sqrtf(fmaxf(rv[r], 0.f));
            float ww = 1.f - fminf(fmaxf((pd - radius) / radius, 0.f), 1.f);
            rowsum += ww * part;
        }
    }
    if (lane == 0) g_part[i] = rowsum;
}

// ---------------------------------------------------------------------------
// Kernel 4: deterministic tree reduction of 4096 partials -> scalar mean
// ---------------------------------------------------------------------------
__global__ void reduce_kernel(float* __restrict__ out) {
    __shared__ float s[1024];
    int t = threadIdx.x;
    float a = g_part[t] + g_part[t + 1024] + g_part[t + 2048] + g_part[t + 3072];
    s[t] = a;
    __syncthreads();
    for (int o = 512; o; o >>= 1) {
        if (t < o) s[t] += s[t + o];
        __syncthreads();
    }
    if (t == 0) out[0] = s[0] * (1.0f / ((float)BB * (float)BB));
}

// ---------------------------------------------------------------------------
extern "C" void kernel_launch(void* const* d_in, const int* in_sizes, int n_in,
                              void* d_out, int out_size) {
    const float* z_i = (const float*)d_in[0];
    const float* z_j = (const float*)d_in[1];
    const float* z_i_prob = (const float*)d_in[2];
    const float* z_j_prob = (const float*)d_in[3];
    const int* pseudo_label = (const int*)d_in[4];
    float* out = (float*)d_out;

    sq_kernel<<<BB / 8, 256>>>(z_i, z_j);
    gemm_d2_kernel<<<528, 256>>>(z_i, z_j);     // 32*33/2 upper-tri tiles
    select_loss_kernel<<<BB / 8, 256>>>(z_i_prob, z_j_prob, pseudo_label);
    reduce_kernel<<<1, 1024>>>(out);
}

// round 4
// speedup vs baseline: 1.8771x; 1.8771x over previous
#include <cuda_runtime.h>
#include <cuda_bf16.h>
#include <math.h>
#include <float.h>
#include <stdint.h>

// Problem constants
#define NS 2048        // n
#define BB 4096        // 2n
#define DD 512         // feature dim
#define CC 128         // num classes
#define KC 12          // candidate count (approx top-12 contains exact top-10)

// Scratch (allocation-free rule: __device__ globals)
__device__ float g_d2[(size_t)BB * BB];                        // 64 MB approx pairwise squared distances
__device__ float g_sq[BB];                                     // exact fp32 row squared norms
__device__ float g_part[BB];                                   // per-row partial sums
__device__ __align__(16) __nv_bfloat16 g_fb[(size_t)BB * DD];  // 4 MB bf16 feats

// ---------------------------------------------------------------------------
// helpers
// ---------------------------------------------------------------------------
__device__ __forceinline__ uint32_t smem_u32(const void* p) {
    uint32_t a;
    asm("{ .reg .u64 t; cvta.to.shared.u64 t, %1; cvt.u32.u64 %0, t; }" : "=r"(a) : "l"(p));
    return a;
}
__device__ __forceinline__ void cp16(uint32_t dst, const void* src) {
    asm volatile("cp.async.cg.shared.global [%0], [%1], 16;" :: "r"(dst), "l"(src) : "memory");
}
#define CP_COMMIT() asm volatile("cp.async.commit_group;" ::: "memory")
#define CP_WAIT(N)  asm volatile("cp.async.wait_group %0;" :: "n"(N) : "memory")

#define LDSM_X4(d, addr) \
    asm volatile("ldmatrix.sync.aligned.m8n8.x4.shared.b16 {%0,%1,%2,%3}, [%4];" \
                 : "=r"((d)[0]), "=r"((d)[1]), "=r"((d)[2]), "=r"((d)[3]) : "r"(addr))

#define MMA16816(c, a, b0, b1) \
    asm volatile("mma.sync.aligned.m16n8k16.row.col.f32.bf16.bf16.f32 " \
                 "{%0,%1,%2,%3}, {%4,%5,%6,%7}, {%8,%9}, {%0,%1,%2,%3};" \
                 : "+f"((c)[0]), "+f"((c)[1]), "+f"((c)[2]), "+f"((c)[3]) \
                 : "r"((a)[0]), "r"((a)[1]), "r"((a)[2]), "r"((a)[3]), "r"(b0), "r"(b1))

// ---------------------------------------------------------------------------
// Kernel 0: fp32 -> bf16 conversion of feats = concat(z_i, z_j)
// ---------------------------------------------------------------------------
__global__ void conv_kernel(const float* __restrict__ zi, const float* __restrict__ zj) {
    int idx = blockIdx.x * blockDim.x + threadIdx.x;
    size_t e = (size_t)idx * 4;
    const float* src = (e < (size_t)NS * DD) ? zi + e : zj + (e - (size_t)NS * DD);
    float4 v = *(const float4*)src;
    __nv_bfloat162 lo = __floats2bfloat162_rn(v.x, v.y);
    __nv_bfloat162 hi = __floats2bfloat162_rn(v.z, v.w);
    *(__nv_bfloat162*)(g_fb + e) = lo;
    *(__nv_bfloat162*)(g_fb + e + 2) = hi;
}

// ---------------------------------------------------------------------------
// Kernel 1: exact fp32 row squared norms. One warp per row.
// ---------------------------------------------------------------------------
__global__ void sq_kernel(const float* __restrict__ zi, const float* __restrict__ zj) {
    int w = (blockIdx.x * blockDim.x + threadIdx.x) >> 5;
    int lane = threadIdx.x & 31;
    if (w >= BB) return;
    const float* p = (w < NS) ? zi + (size_t)w * DD : zj + (size_t)(w - NS) * DD;
    const float4* p4 = (const float4*)p;
    float s = 0.f;
    #pragma unroll
    for (int k = lane; k < DD / 4; k += 32) {
        float4 v = p4[k];
        s += v.x * v.x + v.y * v.y + v.z * v.z + v.w * v.w;
    }
    #pragma unroll
    for (int o = 16; o; o >>= 1) s += __shfl_xor_sync(0xffffffffu, s, o);
    if (lane == 0) g_sq[w] = s;
}

// ---------------------------------------------------------------------------
// Kernel 2: bf16 mma.sync GEMM -> approx d2 (candidate filter).
// 128x128 tile per CTA, BK=32, 8 warps each 64x32, cp.async double buffer.
// ---------------------------------------------------------------------------
#define KT    16            // 512 / 32 k-tiles
#define SROW  40            // smem row stride in bf16 elems (80 B)
#define SBUF  (128 * SROW)  // elems per tile buffer

__global__ void __launch_bounds__(256, 2) gemm_kernel() {
    __shared__ __align__(16) __nv_bfloat16 As[2][SBUF];
    __shared__ __align__(16) __nv_bfloat16 Bs[2][SBUF];
    __shared__ float s_sqm[128], s_sqn[128];

    const int tid = threadIdx.x;
    const int lane = tid & 31;
    const int wid = tid >> 5;
    const int wy = wid >> 2;
    const int wx = wid & 3;
    const int m0 = blockIdx.y << 7;
    const int n0 = blockIdx.x << 7;

    if (tid < 128) { s_sqm[tid] = g_sq[m0 + tid]; s_sqn[tid] = g_sq[n0 + tid]; }

    const int lr = tid >> 1;
    const int lu = (tid & 1) * 16;
    const uint32_t sA = smem_u32(As);
    const uint32_t sB = smem_u32(Bs);
    const uint32_t sdoff = (uint32_t)(lr * SROW + lu) * 2;
    const __nv_bfloat16* gA = g_fb + (size_t)(m0 + lr) * DD + lu;
    const __nv_bfloat16* gB = g_fb + (size_t)(n0 + lr) * DD + lu;

    const int rowA = wy * 64 + (lane & 7) + ((lane >> 3) & 1) * 8;
    const int colA = (lane >> 4) * 8;
    const int rowB = wx * 32 + (lane & 7) + (lane >> 4) * 8;
    const int colB = ((lane >> 3) & 1) * 8;

    float acc[4][4][4];
    #pragma unroll
    for (int i = 0; i < 4; i++)
        #pragma unroll
        for (int j = 0; j < 4; j++)
            #pragma unroll
            for (int q = 0; q < 4; q++) acc[i][j][q] = 0.f;

    {
        cp16(sA + sdoff, gA); cp16(sA + sdoff + 16, gA + 8);
        cp16(sB + sdoff, gB); cp16(sB + sdoff + 16, gB + 8);
        CP_COMMIT();
    }

    for (int kt = 0; kt < KT; ++kt) {
        const int buf = kt & 1;
        if (kt + 1 < KT) {
            const uint32_t boff = (uint32_t)(buf ^ 1) * (SBUF * 2);
            const __nv_bfloat16* pa = gA + (kt + 1) * 32;
            const __nv_bfloat16* pb = gB + (kt + 1) * 32;
            cp16(sA + boff + sdoff, pa); cp16(sA + boff + sdoff + 16, pa + 8);
            cp16(sB + boff + sdoff, pb); cp16(sB + boff + sdoff + 16, pb + 8);
            CP_COMMIT();
            CP_WAIT(1);
        } else {
            CP_WAIT(0);
        }
        __syncthreads();

        const uint32_t ab = sA + (uint32_t)buf * (SBUF * 2);
        const uint32_t bb = sB + (uint32_t)buf * (SBUF * 2);
        #pragma unroll
        for (int ks = 0; ks < 2; ++ks) {
            uint32_t a[4][4], b[2][4];
            #pragma unroll
            for (int mi = 0; mi < 4; mi++)
                LDSM_X4(a[mi], ab + (uint32_t)((rowA + mi * 16) * SROW + ks * 16 + colA) * 2);
            #pragma unroll
            for (int ng = 0; ng < 2; ng++)
                LDSM_X4(b[ng], bb + (uint32_t)((rowB + ng * 16) * SROW + ks * 16 + colB) * 2);
            #pragma unroll
            for (int mi = 0; mi < 4; mi++)
                #pragma unroll
                for (int nb = 0; nb < 4; nb++)
                    MMA16816(acc[mi][nb], a[mi], b[nb >> 1][(nb & 1) * 2], b[nb >> 1][(nb & 1) * 2 + 1]);
        }
        __syncthreads();
    }

    const int er = wy * 64 + (lane >> 2);
    const int ec = wx * 32 + (lane & 3) * 2;
    #pragma unroll
    for (int mi = 0; mi < 4; mi++) {
        const int ra = er + mi * 16;
        const int rb = ra + 8;
        const float sqa = s_sqm[ra];
        const float sqb = s_sqm[rb];
        float* pa = g_d2 + (size_t)(m0 + ra) * BB + n0;
        float* pb = g_d2 + (size_t)(m0 + rb) * BB + n0;
        #pragma unroll
        for (int nb = 0; nb < 4; nb++) {
            const int cc = ec + nb * 8;
            const float sn0 = s_sqn[cc], sn1 = s_sqn[cc + 1];
            *(float2*)(pa + cc) = make_float2(sqa + sn0 - 2.f * acc[mi][nb][0],
                                              sqa + sn1 - 2.f * acc[mi][nb][1]);
            *(float2*)(pb + cc) = make_float2(sqb + sn0 - 2.f * acc[mi][nb][2],
                                              sqb + sn1 - 2.f * acc[mi][nb][3]);
        }
    }
}

// ---------------------------------------------------------------------------
// Kernel 3: approx top-12 candidates -> exact fp32 rescore -> exact top-10,
// weights, masked prob-dots. One warp per row.
// ---------------------------------------------------------------------------
__global__ void select_loss_kernel(const float* __restrict__ zi,
                                   const float* __restrict__ zj,
                                   const float* __restrict__ zip,
                                   const float* __restrict__ zjp,
                                   const int* __restrict__ label) {
    int w = (blockIdx.x * blockDim.x + threadIdx.x) >> 5;
    int lane = threadIdx.x & 31;
    if (w >= BB) return;
    const int i = w;
    const float* drow = g_d2 + (size_t)i * BB;

    // ---- approx scan: per-lane sorted top-12 smallest ----
    float v[KC]; int c[KC];
    #pragma unroll
    for (int q = 0; q < KC; q++) { v[q] = FLT_MAX; c[q] = -1; }

    for (int it = 0; it < BB / 128; ++it) {
        int j4 = lane + it * 32;
        float4 d4 = *(const float4*)(drow + 4 * j4);
        float mn = fminf(fminf(d4.x, d4.y), fminf(d4.z, d4.w));
        if (mn < v[KC - 1]) {
            float dv[4] = {d4.x, d4.y, d4.z, d4.w};
            #pragma unroll
            for (int k = 0; k < 4; k++) {
                int j = 4 * j4 + k;
                float d = dv[k];
                if (j == i || d >= v[KC - 1]) continue;
                v[KC - 1] = d; c[KC - 1] = j;
                #pragma unroll
                for (int q = KC - 1; q >= 1; q--) {
                    if (v[q] < v[q - 1]) {
                        float tv = v[q]; v[q] = v[q - 1]; v[q - 1] = tv;
                        int tc = c[q]; c[q] = c[q - 1]; c[q - 1] = tc;
                    }
                }
            }
        }
    }

    // ---- warp merge: 12 rounds of argmin-extract -> candidate indices ----
    int rc[KC];
    #pragma unroll
    for (int r = 0; r < KC; r++) {
        float mv = v[0]; int mc = c[0];
        #pragma unroll
        for (int o = 16; o; o >>= 1) {
            float ov = __shfl_down_sync(0xffffffffu, mv, o);
            int oc = __shfl_down_sync(0xffffffffu, mc, o);
            if (ov < mv || (ov == mv && (unsigned)oc < (unsigned)mc)) { mv = ov; mc = oc; }
        }
        mc = __shfl_sync(0xffffffffu, mc, 0);
        rc[r] = mc;
        if (c[0] == mc && mc >= 0) {
            #pragma unroll
            for (int q = 0; q < KC - 1; q++) { v[q] = v[q + 1]; c[q] = c[q + 1]; }
            v[KC - 1] = FLT_MAX; c[KC - 1] = -1;
        }
    }

    // ---- exact fp32 rescore of the 12 candidates ----
    const float* fip = (i < NS) ? zi + (size_t)i * DD : zj + (size_t)(i - NS) * DD;
    float4 fi[4];
    #pragma unroll
    for (int q = 0; q < 4; q++) fi[q] = ((const float4*)fip)[lane + 32 * q];
    const float sqi = g_sq[i];

    float rd[KC];
    #pragma unroll
    for (int r = 0; r < KC; r++) {
        int j = rc[r];
        const float* fjp = (j < NS) ? zi + (size_t)j * DD : zj + (size_t)(j - NS) * DD;
        float s = 0.f;
        #pragma unroll
        for (int q = 0; q < 4; q++) {
            float4 fj = ((const float4*)fjp)[lane + 32 * q];
            s += fi[q].x * fj.x + fi[q].y * fj.y + fi[q].z * fj.z + fi[q].w * fj.w;
        }
        #pragma unroll
        for (int o = 16; o; o >>= 1) s += __shfl_xor_sync(0xffffffffu, s, o);
        rd[r] = sqi + g_sq[j] - 2.f * s;           // exact d2 (all lanes agree)
    }

    // ---- per-lane redundant sort of 12 (ascending d2, index tiebreak) ----
    #pragma unroll
    for (int a = 1; a < KC; a++) {
        float dv = rd[a]; int ci = rc[a];
        int b = a;
        while (b > 0 && (rd[b - 1] > dv || (rd[b - 1] == dv && rc[b - 1] > ci))) {
            rd[b] = rd[b - 1]; rc[b] = rc[b - 1]; --b;
        }
        rd[b] = dv; rc[b] = ci;
    }

    // ---- weights + masked prob-dots over exact top-10 ----
    float radius = sqrtf(fmaxf(rd[0], 0.f));
    const float* prow = (i < NS) ? zip + (size_t)i * CC : zjp + (size_t)(i - NS) * CC;
    float4 myp = ((const float4*)prow)[lane];
    const int im = i & (NS - 1);
    const int li = label[im];
    float rowsum = 0.f;
    #pragma unroll
    for (int r = 0; r < 10; r++) {
        int j = rc[r];
        int jm = j & (NS - 1);
        if (li == label[jm] && li != -1 && im != jm) {
            const float* pr = (j < NS) ? zip + (size_t)j * CC : zjp + (size_t)(j - NS) * CC;
            float4 q4 = ((const float4*)pr)[lane];
            float part = myp.x * q4.x + myp.y * q4.y + myp.z * q4.z + myp.w * q4.w;
            #pragma unroll
            for (int o = 16; o; o >>= 1) part += __shfl_xor_sync(0xffffffffu, part, o);
            float pd = sqrtf(fmaxf(rd[r], 0.f));
            float ww = 1.f - fminf(fmaxf((pd - radius) / radius, 0.f), 1.f);
            rowsum += ww * part;
        }
    }
    if (lane == 0) g_part[i] = rowsum;
}

// ---------------------------------------------------------------------------
// Kernel 4: deterministic tree reduction -> scalar mean
// ---------------------------------------------------------------------------
__global__ void reduce_kernel(float* __restrict__ out) {
    __shared__ float s[1024];
    int t = threadIdx.x;
    float a = g_part[t] + g_part[t + 1024] + g_part[t + 2048] + g_part[t + 3072];
    s[t] = a;
    __syncthreads();
    for (int o = 512; o; o >>= 1) {
        if (t < o) s[t] += s[t + o];
        __syncthreads();
    }
    if (t == 0) out[0] = s[0] * (1.0f / ((float)BB * (float)BB));
}

// ---------------------------------------------------------------------------
extern "C" void kernel_launch(void* const* d_in, const int* in_sizes, int n_in,
                              void* d_out, int out_size) {
    const float* z_i = (const float*)d_in[0];
    const float* z_j = (const float*)d_in[1];
    const float* z_i_prob = (const float*)d_in[2];
    const float* z_j_prob = (const float*)d_in[3];
    const int* pseudo_label = (const int*)d_in[4];
    float* out = (float*)d_out;

    conv_kernel<<<(BB * DD / 4) / 256, 256>>>(z_i, z_j);
    sq_kernel<<<BB / 8, 256>>>(z_i, z_j);
    gemm_kernel<<<dim3(32, 32), 256>>>();
    select_loss_kernel<<<BB / 8, 256>>>(z_i, z_j, z_i_prob, z_j_prob, pseudo_label);
    reduce_kernel<<<1, 1024>>>(out);
}

// round 5
// speedup vs baseline: 2.0580x; 1.0964x over previous
#include <cuda_runtime.h>
#include <cuda_bf16.h>
#include <math.h>
#include <float.h>
#include <stdint.h>

// Problem constants
#define NS 2048        // n
#define BB 4096        // 2n
#define DD 512         // feature dim
#define CC 128         // num classes
#define KC 12          // candidates per (row,tile) and final candidate count
#define NT_COL 32      // 4096/128 column tiles

// Scratch (allocation-free rule: __device__ globals)
__device__ float g_sq[BB];                                      // exact fp32 row squared norms
__device__ float g_part[BB];                                    // per-row partial sums
__device__ __align__(16) __nv_bfloat16 g_fb[(size_t)BB * DD];   // 4 MB bf16 feats
__device__ __align__(16) float2 g_cand[(size_t)BB * NT_COL * KC]; // 12.6 MB (d2, colbits)

// ---------------------------------------------------------------------------
// helpers
// ---------------------------------------------------------------------------
__device__ __forceinline__ uint32_t smem_u32(const void* p) {
    uint32_t a;
    asm("{ .reg .u64 t; cvta.to.shared.u64 t, %1; cvt.u32.u64 %0, t; }" : "=r"(a) : "l"(p));
    return a;
}
__device__ __forceinline__ void cp16(uint32_t dst, const void* src) {
    asm volatile("cp.async.cg.shared.global [%0], [%1], 16;" :: "r"(dst), "l"(src) : "memory");
}
#define CP_COMMIT() asm volatile("cp.async.commit_group;" ::: "memory")
#define CP_WAIT(N)  asm volatile("cp.async.wait_group %0;" :: "n"(N) : "memory")

#define LDSM_X4(d, addr) \
    asm volatile("ldmatrix.sync.aligned.m8n8.x4.shared.b16 {%0,%1,%2,%3}, [%4];" \
                 : "=r"((d)[0]), "=r"((d)[1]), "=r"((d)[2]), "=r"((d)[3]) : "r"(addr))

#define MMA16816(c, a, b0, b1) \
    asm volatile("mma.sync.aligned.m16n8k16.row.col.f32.bf16.bf16.f32 " \
                 "{%0,%1,%2,%3}, {%4,%5,%6,%7}, {%8,%9}, {%0,%1,%2,%3};" \
                 : "+f"((c)[0]), "+f"((c)[1]), "+f"((c)[2]), "+f"((c)[3]) \
                 : "r"((a)[0]), "r"((a)[1]), "r"((a)[2]), "r"((a)[3]), "r"(b0), "r"(b1))

// ---------------------------------------------------------------------------
// Kernel 0: fp32 -> bf16 conversion of feats = concat(z_i, z_j)
// ---------------------------------------------------------------------------
__global__ void conv_kernel(const float* __restrict__ zi, const float* __restrict__ zj) {
    int idx = blockIdx.x * blockDim.x + threadIdx.x;
    size_t e = (size_t)idx * 4;
    const float* src = (e < (size_t)NS * DD) ? zi + e : zj + (e - (size_t)NS * DD);
    float4 v = *(const float4*)src;
    __nv_bfloat162 lo = __floats2bfloat162_rn(v.x, v.y);
    __nv_bfloat162 hi = __floats2bfloat162_rn(v.z, v.w);
    *(__nv_bfloat162*)(g_fb + e) = lo;
    *(__nv_bfloat162*)(g_fb + e + 2) = hi;
}

// ---------------------------------------------------------------------------
// Kernel 1: exact fp32 row squared norms. One warp per row.
// ---------------------------------------------------------------------------
__global__ void sq_kernel(const float* __restrict__ zi, const float* __restrict__ zj) {
    int w = (blockIdx.x * blockDim.x + threadIdx.x) >> 5;
    int lane = threadIdx.x & 31;
    if (w >= BB) return;
    const float* p = (w < NS) ? zi + (size_t)w * DD : zj + (size_t)(w - NS) * DD;
    const float4* p4 = (const float4*)p;
    float s = 0.f;
    #pragma unroll
    for (int k = lane; k < DD / 4; k += 32) {
        float4 v = p4[k];
        s += v.x * v.x + v.y * v.y + v.z * v.z + v.w * v.w;
    }
    #pragma unroll
    for (int o = 16; o; o >>= 1) s += __shfl_xor_sync(0xffffffffu, s, o);
    if (lane == 0) g_sq[w] = s;
}

// ---------------------------------------------------------------------------
// Kernel 2: bf16 mma.sync GEMM (128x128 tile) + fused per-(row,tile) top-12
// selection in the epilogue. No d2 matrix is ever written to global memory.
// ---------------------------------------------------------------------------
#define KT    16            // 512 / 32 k-tiles
#define SROW  40            // smem row stride in bf16 elems (80 B)
#define SBUF  (128 * SROW)  // elems per tile buffer (5120)
#define STG_STRIDE 132      // stage row stride in floats (conflict-free)

__global__ void __launch_bounds__(256, 2) gemm_select_kernel() {
    // union: A/B double buffers (40960 B) overlap the 64x132 f32 stage (33792 B)
    __shared__ __align__(16) char sraw[40960];
    __shared__ float s_sqm[128], s_sqn[128];

    __nv_bfloat16* As = (__nv_bfloat16*)sraw;             // [2][SBUF]
    __nv_bfloat16* Bs = (__nv_bfloat16*)(sraw + 20480);   // [2][SBUF]
    float* stg = (float*)sraw;                            // [64][132]

    const int tid = threadIdx.x;
    const int lane = tid & 31;
    const int wid = tid >> 5;
    const int wy = wid >> 2;
    const int wx = wid & 3;
    const int m0 = blockIdx.y << 7;
    const int n0 = blockIdx.x << 7;
    const int bj = blockIdx.x;

    if (tid < 128) { s_sqm[tid] = g_sq[m0 + tid]; s_sqn[tid] = g_sq[n0 + tid]; }

    const int lr = tid >> 1;
    const int lu = (tid & 1) * 16;
    const uint32_t sA = smem_u32(As);
    const uint32_t sB = smem_u32(Bs);
    const uint32_t sdoff = (uint32_t)(lr * SROW + lu) * 2;
    const __nv_bfloat16* gA = g_fb + (size_t)(m0 + lr) * DD + lu;
    const __nv_bfloat16* gB = g_fb + (size_t)(n0 + lr) * DD + lu;

    const int rowA = wy * 64 + (lane & 7) + ((lane >> 3) & 1) * 8;
    const int colA = (lane >> 4) * 8;
    const int rowB = wx * 32 + (lane & 7) + (lane >> 4) * 8;
    const int colB = ((lane >> 3) & 1) * 8;

    float acc[4][4][4];
    #pragma unroll
    for (int i = 0; i < 4; i++)
        #pragma unroll
        for (int j = 0; j < 4; j++)
            #pragma unroll
            for (int q = 0; q < 4; q++) acc[i][j][q] = 0.f;

    {
        cp16(sA + sdoff, gA); cp16(sA + sdoff + 16, gA + 8);
        cp16(sB + sdoff, gB); cp16(sB + sdoff + 16, gB + 8);
        CP_COMMIT();
    }

    for (int kt = 0; kt < KT; ++kt) {
        const int buf = kt & 1;
        if (kt + 1 < KT) {
            const uint32_t boff = (uint32_t)(buf ^ 1) * (SBUF * 2);
            const __nv_bfloat16* pa = gA + (kt + 1) * 32;
            const __nv_bfloat16* pb = gB + (kt + 1) * 32;
            cp16(sA + boff + sdoff, pa); cp16(sA + boff + sdoff + 16, pa + 8);
            cp16(sB + boff + sdoff, pb); cp16(sB + boff + sdoff + 16, pb + 8);
            CP_COMMIT();
            CP_WAIT(1);
        } else {
            CP_WAIT(0);
        }
        __syncthreads();

        const uint32_t ab = sA + (uint32_t)buf * (SBUF * 2);
        const uint32_t bb = sB + (uint32_t)buf * (SBUF * 2);
        #pragma unroll
        for (int ks = 0; ks < 2; ++ks) {
            uint32_t a[4][4], b[2][4];
            #pragma unroll
            for (int mi = 0; mi < 4; mi++)
                LDSM_X4(a[mi], ab + (uint32_t)((rowA + mi * 16) * SROW + ks * 16 + colA) * 2);
            #pragma unroll
            for (int ng = 0; ng < 2; ng++)
                LDSM_X4(b[ng], bb + (uint32_t)((rowB + ng * 16) * SROW + ks * 16 + colB) * 2);
            #pragma unroll
            for (int mi = 0; mi < 4; mi++)
                #pragma unroll
                for (int nb = 0; nb < 4; nb++)
                    MMA16816(acc[mi][nb], a[mi], b[nb >> 1][(nb & 1) * 2], b[nb >> 1][(nb & 1) * 2 + 1]);
        }
        __syncthreads();
    }
    // (loop-tail __syncthreads guarantees all ldsm reads done; A/B smem now dead)

    // ---- fused epilogue: two 64-row passes of stage + per-row top-12 ----
    const int g8 = lane >> 2;       // quad id within warp: 0..7
    const int l4 = lane & 3;        // lane within quad

    #pragma unroll 1
    for (int half = 0; half < 2; ++half) {
        // stage d2 for rows [half*64, half*64+64) of this tile
        if (wy == half) {
            const int er = (lane >> 2);          // 0..7
            const int ec = wx * 32 + (lane & 3) * 2;
            #pragma unroll
            for (int mi = 0; mi < 4; mi++) {
                const int ra = mi * 16 + er;     // relative row in this half
                const int rb = ra + 8;
                const float sqa = s_sqm[half * 64 + ra];
                const float sqb = s_sqm[half * 64 + rb];
                #pragma unroll
                for (int nb = 0; nb < 4; nb++) {
                    const int cc = ec + nb * 8;
                    const float sn0 = s_sqn[cc], sn1 = s_sqn[cc + 1];
                    stg[ra * STG_STRIDE + cc]     = sqa + sn0 - 2.f * acc[mi][nb][0];
                    stg[ra * STG_STRIDE + cc + 1] = sqa + sn1 - 2.f * acc[mi][nb][1];
                    stg[rb * STG_STRIDE + cc]     = sqb + sn0 - 2.f * acc[mi][nb][2];
                    stg[rb * STG_STRIDE + cc + 1] = sqb + sn1 - 2.f * acc[mi][nb][3];
                }
            }
        }
        __syncthreads();

        // selection: warp 'wid' handles rows wid*8 .. wid*8+8 (one per quad)
        const int relrow = wid * 8 + g8;                 // 0..63
        const int grow = m0 + half * 64 + relrow;

        float v[KC]; int c[KC];
        #pragma unroll
        for (int q = 0; q < KC; q++) { v[q] = FLT_MAX; c[q] = 0x7fffffff; }

        const float* srow = stg + relrow * STG_STRIDE;
        #pragma unroll 4
        for (int q = 0; q < 32; ++q) {
            const int col = l4 + 4 * q;
            const float d = srow[col];
            const int gcol = n0 + col;
            if (gcol != grow && d < v[KC - 1]) {
                v[KC - 1] = d; c[KC - 1] = gcol;
                #pragma unroll
                for (int s = KC - 1; s >= 1; s--) {
                    if (v[s] < v[s - 1]) {
                        float tv = v[s]; v[s] = v[s - 1]; v[s - 1] = tv;
                        int tc = c[s]; c[s] = c[s - 1]; c[s - 1] = tc;
                    }
                }
            }
        }

        // 4-lane (quad) merge: 12 extract rounds, direct stores from quad leader
        float2* crow = g_cand + ((size_t)grow * NT_COL + bj) * KC;
        #pragma unroll
        for (int r = 0; r < KC; ++r) {
            float mv = v[0]; int mc = c[0];
            #pragma unroll
            for (int o = 1; o <= 2; o <<= 1) {
                float ov = __shfl_xor_sync(0xffffffffu, mv, o);
                int oc = __shfl_xor_sync(0xffffffffu, mc, o);
                if (ov < mv || (ov == mv && oc < mc)) { mv = ov; mc = oc; }
            }
            if (c[0] == mc) {   // unique owner pops its head
                #pragma unroll
                for (int s = 0; s < KC - 1; s++) { v[s] = v[s + 1]; c[s] = c[s + 1]; }
                v[KC - 1] = FLT_MAX; c[KC - 1] = 0x7fffffff;
            }
            if (l4 == 0) crow[r] = make_float2(mv, __int_as_float(mc));
        }
        __syncthreads();   // stage buffer free before next half's stores
    }
}

// ---------------------------------------------------------------------------
// Kernel 3: merge 32x12 per-tile candidates -> approx top-12 -> exact fp32
// rescore -> exact top-10 -> weights, masked prob-dots. One warp per row.
// ---------------------------------------------------------------------------
__global__ void merge_loss_kernel(const float* __restrict__ zi,
                                  const float* __restrict__ zj,
                                  const float* __restrict__ zip,
                                  const float* __restrict__ zjp,
                                  const int* __restrict__ label) {
    int w = (blockIdx.x * blockDim.x + threadIdx.x) >> 5;
    int lane = threadIdx.x & 31;
    if (w >= BB) return;
    const int i = w;
    const float2* crow = g_cand + (size_t)i * (NT_COL * KC);

    // per-lane sorted top-12 over its 12 assigned candidates
    float v[KC]; int c[KC];
    #pragma unroll
    for (int q = 0; q < KC; q++) { v[q] = FLT_MAX; c[q] = 0x7fffffff; }
    #pragma unroll
    for (int t = 0; t < KC; ++t) {
        float2 e = crow[t * 32 + lane];
        float d = e.x;
        int idx = __float_as_int(e.y);
        if (d < v[KC - 1]) {
            v[KC - 1] = d; c[KC - 1] = idx;
            #pragma unroll
            for (int q = KC - 1; q >= 1; q--) {
                if (v[q] < v[q - 1]) {
                    float tv = v[q]; v[q] = v[q - 1]; v[q - 1] = tv;
                    int tc = c[q]; c[q] = c[q - 1]; c[q - 1] = tc;
                }
            }
        }
    }

    // full-warp merge: 12 rounds of argmin-extract
    int rc[KC];
    #pragma unroll
    for (int r = 0; r < KC; r++) {
        float mv = v[0]; int mc = c[0];
        #pragma unroll
        for (int o = 16; o; o >>= 1) {
            float ov = __shfl_down_sync(0xffffffffu, mv, o);
            int oc = __shfl_down_sync(0xffffffffu, mc, o);
            if (ov < mv || (ov == mv && oc < mc)) { mv = ov; mc = oc; }
        }
        mc = __shfl_sync(0xffffffffu, mc, 0);
        rc[r] = mc;
        if (c[0] == mc) {
            #pragma unroll
            for (int q = 0; q < KC - 1; q++) { v[q] = v[q + 1]; c[q] = c[q + 1]; }
            v[KC - 1] = FLT_MAX; c[KC - 1] = 0x7fffffff;
        }
    }

    // exact fp32 rescore of the 12 candidates
    const float* fip = (i < NS) ? zi + (size_t)i * DD : zj + (size_t)(i - NS) * DD;
    float4 fi[4];
    #pragma unroll
    for (int q = 0; q < 4; q++) fi[q] = ((const float4*)fip)[lane + 32 * q];
    const float sqi = g_sq[i];

    float rd[KC];
    #pragma unroll
    for (int r = 0; r < KC; r++) {
        int j = rc[r];
        const float* fjp = (j < NS) ? zi + (size_t)j * DD : zj + (size_t)(j - NS) * DD;
        float s = 0.f;
        #pragma unroll
        for (int q = 0; q < 4; q++) {
            float4 fj = ((const float4*)fjp)[lane + 32 * q];
            s += fi[q].x * fj.x + fi[q].y * fj.y + fi[q].z * fj.z + fi[q].w * fj.w;
        }
        #pragma unroll
        for (int o = 16; o; o >>= 1) s += __shfl_xor_sync(0xffffffffu, s, o);
        rd[r] = sqi + g_sq[j] - 2.f * s;           // exact d2 (all lanes agree)
    }

    // per-lane redundant sort of 12 (ascending d2, index tiebreak)
    #pragma unroll
    for (int a = 1; a < KC; a++) {
        float dv = rd[a]; int ci = rc[a];
        int b = a;
        while (b > 0 && (rd[b - 1] > dv || (rd[b - 1] == dv && rc[b - 1] > ci))) {
            rd[b] = rd[b - 1]; rc[b] = rc[b - 1]; --b;
        }
        rd[b] = dv; rc[b] = ci;
    }

    // weights + masked prob-dots over exact top-10
    float radius = sqrtf(fmaxf(rd[0], 0.f));
    const float* prow = (i < NS) ? zip + (size_t)i * CC : zjp + (size_t)(i - NS) * CC;
    float4 myp = ((const float4*)prow)[lane];
    const int im = i & (NS - 1);
    const int li = label[im];
    float rowsum = 0.f;
    #pragma unroll
    for (int r = 0; r < 10; r++) {
        int j = rc[r];
        int jm = j & (NS - 1);
        if (li == label[jm] && li != -1 && im != jm) {
            const float* pr = (j < NS) ? zip + (size_t)j * CC : zjp + (size_t)(j - NS) * CC;
            float4 q4 = ((const float4*)pr)[lane];
            float part = myp.x * q4.x + myp.y * q4.y + myp.z * q4.z + myp.w * q4.w;
            #pragma unroll
            for (int o = 16; o; o >>= 1) part += __shfl_xor_sync(0xffffffffu, part, o);
            float pd = sqrtf(fmaxf(rd[r], 0.f));
            float ww = 1.f - fminf(fmaxf((pd - radius) / radius, 0.f), 1.f);
            rowsum += ww * part;
        }
    }
    if (lane == 0) g_part[i] = rowsum;
}

// ---------------------------------------------------------------------------
// Kernel 4: deterministic tree reduction -> scalar mean
// ---------------------------------------------------------------------------
__global__ void reduce_kernel(float* __restrict__ out) {
    __shared__ float s[1024];
    int t = threadIdx.x;
    float a = g_part[t] + g_part[t + 1024] + g_part[t + 2048] + g_part[t + 3072];
    s[t] = a;
    __syncthreads();
    for (int o = 512; o; o >>= 1) {
        if (t < o) s[t] += s[t + o];
        __syncthreads();
    }
    if (t == 0) out[0] = s[0] * (1.0f / ((float)BB * (float)BB));
}

// ---------------------------------------------------------------------------
extern "C" void kernel_launch(void* const* d_in, const int* in_sizes, int n_in,
                              void* d_out, int out_size) {
    const float* z_i = (const float*)d_in[0];
    const float* z_j = (const float*)d_in[1];
    const float* z_i_prob = (const float*)d_in[2];
    const float* z_j_prob = (const float*)d_in[3];
    const int* pseudo_label = (const int*)d_in[4];
    float* out = (float*)d_out;

    conv_kernel<<<(BB * DD / 4) / 256, 256>>>(z_i, z_j);
    sq_kernel<<<BB / 8, 256>>>(z_i, z_j);
    gemm_select_kernel<<<dim3(32, 32), 256>>>();
    merge_loss_kernel<<<BB / 8, 256>>>(z_i, z_j, z_i_prob, z_j_prob, pseudo_label);
    reduce_kernel<<<1, 1024>>>(out);
}

// round 7
// speedup vs baseline: 2.1888x; 1.0636x over previous
#include <cuda_runtime.h>
#include <cuda_bf16.h>
#include <math.h>
#include <float.h>
#include <stdint.h>

// Problem constants
#define NS 2048        // n
#define BB 4096        // 2n
#define DD 512         // feature dim
#define CC 128         // num classes
#define KC 12          // candidates per (row,tile) and final candidate count
#define NT_COL 32      // 4096/128 column tiles

// Scratch (allocation-free rule: __device__ globals)
__device__ float g_sq[BB];                                        // exact fp32 row squared norms
__device__ float g_part[BB];                                      // per-row partial sums
__device__ __align__(16) __nv_bfloat16 g_fb[(size_t)BB * DD];     // 4 MB bf16 feats
__device__ __align__(16) float2 g_cand[(size_t)BB * NT_COL * KC]; // 12.6 MB (score, colbits)

// ---------------------------------------------------------------------------
// helpers
// ---------------------------------------------------------------------------
__device__ __forceinline__ uint32_t smem_u32(const void* p) {
    uint32_t a;
    asm("{ .reg .u64 t; cvta.to.shared.u64 t, %1; cvt.u32.u64 %0, t; }" : "=r"(a) : "l"(p));
    return a;
}
__device__ __forceinline__ void cp16(uint32_t dst, const void* src) {
    asm volatile("cp.async.cg.shared.global [%0], [%1], 16;" :: "r"(dst), "l"(src) : "memory");
}
#define CP_COMMIT() asm volatile("cp.async.commit_group;" ::: "memory")
#define CP_WAIT(N)  asm volatile("cp.async.wait_group %0;" :: "n"(N) : "memory")

#define LDSM_X4(d, addr) \
    asm volatile("ldmatrix.sync.aligned.m8n8.x4.shared.b16 {%0,%1,%2,%3}, [%4];" \
                 : "=r"((d)[0]), "=r"((d)[1]), "=r"((d)[2]), "=r"((d)[3]) : "r"(addr))

#define MMA16816(c, a, b0, b1) \
    asm volatile("mma.sync.aligned.m16n8k16.row.col.f32.bf16.bf16.f32 " \
                 "{%0,%1,%2,%3}, {%4,%5,%6,%7}, {%8,%9}, {%0,%1,%2,%3};" \
                 : "+f"((c)[0]), "+f"((c)[1]), "+f"((c)[2]), "+f"((c)[3]) \
                 : "r"((a)[0]), "r"((a)[1]), "r"((a)[2]), "r"((a)[3]), "r"(b0), "r"(b1))

// ---------------------------------------------------------------------------
// Kernel 0: fp32 -> bf16 conversion of feats = concat(z_i, z_j)
// ---------------------------------------------------------------------------
__global__ void conv_kernel(const float* __restrict__ zi, const float* __restrict__ zj) {
    int idx = blockIdx.x * blockDim.x + threadIdx.x;
    size_t e = (size_t)idx * 4;
    const float* src = (e < (size_t)NS * DD) ? zi + e : zj + (e - (size_t)NS * DD);
    float4 v = *(const float4*)src;
    __nv_bfloat162 lo = __floats2bfloat162_rn(v.x, v.y);
    __nv_bfloat162 hi = __floats2bfloat162_rn(v.z, v.w);
    *(__nv_bfloat162*)(g_fb + e) = lo;
    *(__nv_bfloat162*)(g_fb + e + 2) = hi;
}

// ---------------------------------------------------------------------------
// Kernel 1: exact fp32 row squared norms. One warp per row.
// ---------------------------------------------------------------------------
__global__ void sq_kernel(const float* __restrict__ zi, const float* __restrict__ zj) {
    int w = (blockIdx.x * blockDim.x + threadIdx.x) >> 5;
    int lane = threadIdx.x & 31;
    if (w >= BB) return;
    const float* p = (w < NS) ? zi + (size_t)w * DD : zj + (size_t)(w - NS) * DD;
    const float4* p4 = (const float4*)p;
    float s = 0.f;
    #pragma unroll
    for (int k = lane; k < DD / 4; k += 32) {
        float4 v = p4[k];
        s += v.x * v.x + v.y * v.y + v.z * v.z + v.w * v.w;
    }
    #pragma unroll
    for (int o = 16; o; o >>= 1) s += __shfl_xor_sync(0xffffffffu, s, o);
    if (lane == 0) g_sq[w] = s;
}

// ---------------------------------------------------------------------------
// Kernel 2: bf16 mma.sync GEMM (128x128 tile) + fused per-(row,tile) top-12.
// Stages the FULL tile score (sn - 2*dot) to smem first so acc registers die
// before the selection runs (no register-lifetime overlap -> no spills).
// ---------------------------------------------------------------------------
#define KT    16            // 512 / 32 k-tiles
#define SROW  40            // smem row stride in bf16 elems (80 B)
#define SBUF  (128 * SROW)  // elems per tile buffer (5120)
#define STG_STRIDE 132      // stage row stride in floats
#define DYN_SMEM (128 * STG_STRIDE * 4)   // 67584 B (also covers the 40960 B A/B bufs)

__global__ void __launch_bounds__(256, 2) gemm_select_kernel() {
    extern __shared__ __align__(16) char dsm[];
    __shared__ float s_sqn[128];

    __nv_bfloat16* As = (__nv_bfloat16*)dsm;             // [2][SBUF]
    __nv_bfloat16* Bs = (__nv_bfloat16*)(dsm + 20480);   // [2][SBUF]
    float* stg = (float*)dsm;                            // [128][132]

    const int tid = threadIdx.x;
    const int lane = tid & 31;
    const int wid = tid >> 5;
    const int wy = wid >> 2;
    const int wx = wid & 3;
    const int m0 = blockIdx.y << 7;
    const int n0 = blockIdx.x << 7;
    const int bj = blockIdx.x;

    if (tid < 128) s_sqn[tid] = g_sq[n0 + tid];

    const int lr = tid >> 1;
    const int lu = (tid & 1) * 16;
    const uint32_t sA = smem_u32(As);
    const uint32_t sB = smem_u32(Bs);
    const uint32_t sdoff = (uint32_t)(lr * SROW + lu) * 2;
    const __nv_bfloat16* gA = g_fb + (size_t)(m0 + lr) * DD + lu;
    const __nv_bfloat16* gB = g_fb + (size_t)(n0 + lr) * DD + lu;

    const int rowA = wy * 64 + (lane & 7) + ((lane >> 3) & 1) * 8;
    const int colA = (lane >> 4) * 8;
    const int rowB = wx * 32 + (lane & 7) + (lane >> 4) * 8;
    const int colB = ((lane >> 3) & 1) * 8;

    float acc[4][4][4];
    #pragma unroll
    for (int i = 0; i < 4; i++)
        #pragma unroll
        for (int j = 0; j < 4; j++)
            #pragma unroll
            for (int q = 0; q < 4; q++) acc[i][j][q] = 0.f;

    {
        cp16(sA + sdoff, gA); cp16(sA + sdoff + 16, gA + 8);
        cp16(sB + sdoff, gB); cp16(sB + sdoff + 16, gB + 8);
        CP_COMMIT();
    }

    for (int kt = 0; kt < KT; ++kt) {
        const int buf = kt & 1;
        if (kt + 1 < KT) {
            const uint32_t boff = (uint32_t)(buf ^ 1) * (SBUF * 2);
            const __nv_bfloat16* pa = gA + (kt + 1) * 32;
            const __nv_bfloat16* pb = gB + (kt + 1) * 32;
            cp16(sA + boff + sdoff, pa); cp16(sA + boff + sdoff + 16, pa + 8);
            cp16(sB + boff + sdoff, pb); cp16(sB + boff + sdoff + 16, pb + 8);
            CP_COMMIT();
            CP_WAIT(1);
        } else {
            CP_WAIT(0);
        }
        __syncthreads();

        const uint32_t ab = sA + (uint32_t)buf * (SBUF * 2);
        const uint32_t bb = sB + (uint32_t)buf * (SBUF * 2);
        #pragma unroll
        for (int ks = 0; ks < 2; ++ks) {
            uint32_t a[4][4], b[2][4];
            #pragma unroll
            for (int mi = 0; mi < 4; mi++)
                LDSM_X4(a[mi], ab + (uint32_t)((rowA + mi * 16) * SROW + ks * 16 + colA) * 2);
            #pragma unroll
            for (int ng = 0; ng < 2; ng++)
                LDSM_X4(b[ng], bb + (uint32_t)((rowB + ng * 16) * SROW + ks * 16 + colB) * 2);
            #pragma unroll
            for (int mi = 0; mi < 4; mi++)
                #pragma unroll
                for (int nb = 0; nb < 4; nb++)
                    MMA16816(acc[mi][nb], a[mi], b[nb >> 1][(nb & 1) * 2], b[nb >> 1][(nb & 1) * 2 + 1]);
        }
        __syncthreads();
    }
    // A/B smem dead; all acc staged at once so acc registers die here.

    {
        const int er = (lane >> 2);
        const int ec = wx * 32 + (lane & 3) * 2;
        #pragma unroll
        for (int mi = 0; mi < 4; mi++) {
            const int ra = wy * 64 + mi * 16 + er;
            const int rb = ra + 8;
            #pragma unroll
            for (int nb = 0; nb < 4; nb++) {
                const int cc = ec + nb * 8;
                const float sn0 = s_sqn[cc], sn1 = s_sqn[cc + 1];
                stg[ra * STG_STRIDE + cc]     = sn0 - 2.f * acc[mi][nb][0];
                stg[ra * STG_STRIDE + cc + 1] = sn1 - 2.f * acc[mi][nb][1];
                stg[rb * STG_STRIDE + cc]     = sn0 - 2.f * acc[mi][nb][2];
                stg[rb * STG_STRIDE + cc + 1] = sn1 - 2.f * acc[mi][nb][3];
            }
        }
    }
    __syncthreads();

    // ---- selection: quad per row, 2 row-passes (8 rows per warp per pass) ----
    const int g8 = lane >> 2;
    const int l4 = lane & 3;

    #pragma unroll 1
    for (int rp = 0; rp < 2; ++rp) {
        const int relrow = rp * 64 + wid * 8 + g8;     // 0..127
        const int grow = m0 + relrow;

        float v[KC]; int c[KC];
        #pragma unroll
        for (int q = 0; q < KC; q++) { v[q] = FLT_MAX; c[q] = 0x7fffffff; }

        const float* srow = stg + relrow * STG_STRIDE;
        #pragma unroll
        for (int q = 0; q < 8; ++q) {
            float4 d4 = *(const float4*)(srow + q * 16 + l4 * 4);
            const int cb = n0 + q * 16 + l4 * 4;
            float dv[4] = {d4.x, d4.y, d4.z, d4.w};
            #pragma unroll
            for (int k = 0; k < 4; k++) {
                const int gcol = cb + k;
                const float d = dv[k];
                if (gcol != grow && d < v[KC - 1]) {
                    v[KC - 1] = d; c[KC - 1] = gcol;
                    #pragma unroll
                    for (int s = KC - 1; s >= 1; s--) {
                        if (v[s] < v[s - 1]) {
                            float tv = v[s]; v[s] = v[s - 1]; v[s - 1] = tv;
                            int tc = c[s]; c[s] = c[s - 1]; c[s - 1] = tc;
                        }
                    }
                }
            }
        }

        // quad merge: 12 extract rounds; quad leader stores
        float2* crow = g_cand + ((size_t)grow * NT_COL + bj) * KC;
        #pragma unroll
        for (int r = 0; r < KC; ++r) {
            float mv = v[0]; int mc = c[0];
            #pragma unroll
            for (int o = 1; o <= 2; o <<= 1) {
                float ov = __shfl_xor_sync(0xffffffffu, mv, o);
                int oc = __shfl_xor_sync(0xffffffffu, mc, o);
                if (ov < mv || (ov == mv && oc < mc)) { mv = ov; mc = oc; }
            }
            if (c[0] == mc) {   // unique owner pops its head
                #pragma unroll
                for (int s = 0; s < KC - 1; s++) { v[s] = v[s + 1]; c[s] = c[s + 1]; }
                v[KC - 1] = FLT_MAX; c[KC - 1] = 0x7fffffff;
            }
            if (l4 == 0) crow[r] = make_float2(mv, __int_as_float(mc));
        }
    }
}

// ---------------------------------------------------------------------------
// Kernel 3: merge 32x12 per-tile candidates -> approx top-12 -> exact fp32
// rescore -> exact top-10 -> weights, masked prob-dots. One warp per row.
// ---------------------------------------------------------------------------
__global__ void merge_loss_kernel(const float* __restrict__ zi,
                                  const float* __restrict__ zj,
                                  const float* __restrict__ zip,
                                  const float* __restrict__ zjp,
                                  const int* __restrict__ label) {
    int w = (blockIdx.x * blockDim.x + threadIdx.x) >> 5;
    int lane = threadIdx.x & 31;
    if (w >= BB) return;
    const int i = w;
    const float2* crow = g_cand + (size_t)i * (NT_COL * KC);

    // per-lane sorted top-12 over its 12 assigned candidates
    float v[KC]; int c[KC];
    #pragma unroll
    for (int q = 0; q < KC; q++) { v[q] = FLT_MAX; c[q] = 0x7fffffff; }
    #pragma unroll
    for (int t = 0; t < KC; ++t) {
        float2 e = crow[t * 32 + lane];
        float d = e.x;
        int idx = __float_as_int(e.y);
        if (d < v[KC - 1]) {
            v[KC - 1] = d; c[KC - 1] = idx;
            #pragma unroll
            for (int q = KC - 1; q >= 1; q--) {
                if (v[q] < v[q - 1]) {
                    float tv = v[q]; v[q] = v[q - 1]; v[q - 1] = tv;
                    int tc = c[q]; c[q] = c[q - 1]; c[q - 1] = tc;
                }
            }
        }
    }

    // full-warp merge: 12 rounds of argmin-extract
    int rc[KC];
    #pragma unroll
    for (int r = 0; r < KC; r++) {
        float mv = v[0]; int mc = c[0];
        #pragma unroll
        for (int o = 16; o; o >>= 1) {
            float ov = __shfl_down_sync(0xffffffffu, mv, o);
            int oc = __shfl_down_sync(0xffffffffu, mc, o);
            if (ov < mv || (ov == mv && oc < mc)) { mv = ov; mc = oc; }
        }
        mc = __shfl_sync(0xffffffffu, mc, 0);
        rc[r] = mc;
        if (c[0] == mc) {
            #pragma unroll
            for (int q = 0; q < KC - 1; q++) { v[q] = v[q + 1]; c[q] = c[q + 1]; }
            v[KC - 1] = FLT_MAX; c[KC - 1] = 0x7fffffff;
        }
    }

    // exact fp32 rescore of the 12 candidates
    const float* fip = (i < NS) ? zi + (size_t)i * DD : zj + (size_t)(i - NS) * DD;
    float4 fi[4];
    #pragma unroll
    for (int q = 0; q < 4; q++) fi[q] = ((const float4*)fip)[lane + 32 * q];
    const float sqi = g_sq[i];

    float rd[KC];
    #pragma unroll
    for (int r = 0; r < KC; r++) {
        int j = rc[r];
        const float* fjp = (j < NS) ? zi + (size_t)j * DD : zj + (size_t)(j - NS) * DD;
        float s = 0.f;
        #pragma unroll
        for (int q = 0; q < 4; q++) {
            float4 fj = ((const float4*)fjp)[lane + 32 * q];
            s += fi[q].x * fj.x + fi[q].y * fj.y + fi[q].z * fj.z + fi[q].w * fj.w;
        }
        #pragma unroll
        for (int o = 16; o; o >>= 1) s += __shfl_xor_sync(0xffffffffu, s, o);
        rd[r] = sqi + g_sq[j] - 2.f * s;           // exact d2 (all lanes agree)
    }

    // per-lane redundant sort of 12 (ascending d2, index tiebreak)
    #pragma unroll
    for (int a = 1; a < KC; a++) {
        float dv = rd[a]; int ci = rc[a];
        int b = a;
        while (b > 0 && (rd[b - 1] > dv || (rd[b - 1] == dv && rc[b - 1] > ci))) {
            rd[b] = rd[b - 1]; rc[b] = rc[b - 1]; --b;
        }
        rd[b] = dv; rc[b] = ci;
    }

    // weights + masked prob-dots over exact top-10
    float radius = sqrtf(fmaxf(rd[0], 0.f));
    const float* prow = (i < NS) ? zip + (size_t)i * CC : zjp + (size_t)(i - NS) * CC;
    float4 myp = ((const float4*)prow)[lane];
    const int im = i & (NS - 1);
    const int li = label[im];
    float rowsum = 0.f;
    #pragma unroll
    for (int r = 0; r < 10; r++) {
        int j = rc[r];
        int jm = j & (NS - 1);
        if (li == label[jm] && li != -1 && im != jm) {
            const float* pr = (j < NS) ? zip + (size_t)j * CC : zjp + (size_t)(j - NS) * CC;
            float4 q4 = ((const float4*)pr)[lane];
            float part = myp.x * q4.x + myp.y * q4.y + myp.z * q4.z + myp.w * q4.w;
            #pragma unroll
            for (int o = 16; o; o >>= 1) part += __shfl_xor_sync(0xffffffffu, part, o);
            float pd = sqrtf(fmaxf(rd[r], 0.f));
            float ww = 1.f - fminf(fmaxf((pd - radius) / radius, 0.f), 1.f);
            rowsum += ww * part;
        }
    }
    if (lane == 0) g_part[i] = rowsum;
}

// ---------------------------------------------------------------------------
// Kernel 4: deterministic tree reduction -> scalar mean
// ---------------------------------------------------------------------------
__global__ void reduce_kernel(float* __restrict__ out) {
    __shared__ float s[1024];
    int t = threadIdx.x;
    float a = g_part[t] + g_part[t + 1024] + g_part[t + 2048] + g_part[t + 3072];
    s[t] = a;
    __syncthreads();
    for (int o = 512; o; o >>= 1) {
        if (t < o) s[t] += s[t + o];
        __syncthreads();
    }
    if (t == 0) out[0] = s[0] * (1.0f / ((float)BB * (float)BB));
}

// ---------------------------------------------------------------------------
extern "C" void kernel_launch(void* const* d_in, const int* in_sizes, int n_in,
                              void* d_out, int out_size) {
    const float* z_i = (const float*)d_in[0];
    const float* z_j = (const float*)d_in[1];
    const float* z_i_prob = (const float*)d_in[2];
    const float* z_j_prob = (const float*)d_in[3];
    const int* pseudo_label = (const int*)d_in[4];
    float* out = (float*)d_out;

    cudaFuncSetAttribute(gemm_select_kernel,
                         cudaFuncAttributeMaxDynamicSharedMemorySize, DYN_SMEM);

    conv_kernel<<<(BB * DD / 4) / 256, 256>>>(z_i, z_j);
    sq_kernel<<<BB / 8, 256>>>(z_i, z_j);
    gemm_select_kernel<<<dim3(32, 32), 256, DYN_SMEM>>>();
    merge_loss_kernel<<<BB / 8, 256>>>(z_i, z_j, z_i_prob, z_j_prob, pseudo_label);
    reduce_kernel<<<1, 1024>>>(out);
}

// round 8
// speedup vs baseline: 2.6117x; 1.1932x over previous
#include <cuda_runtime.h>
#include <cuda_bf16.h>
#include <math.h>
#include <float.h>
#include <stdint.h>

// Problem constants
#define NS 2048        // n
#define BB 4096        // 2n
#define DD 512         // feature dim
#define CC 128         // num classes
#define KC 12          // candidates per (row,tile) and final candidate count
#define NT_COL 32      // 4096/128 column tiles

// Scratch (allocation-free rule: __device__ globals)
__device__ float g_sq[BB];                                          // exact fp32 row squared norms
__device__ float g_part[BB];                                        // per-row partial sums
__device__ __align__(16) __nv_bfloat16 g_fb[(size_t)BB * DD];       // 4 MB bf16 feats
__device__ __align__(16) uint32_t g_cand[(size_t)BB * NT_COL * KC]; // 6.3 MB packed keys

// ---------------------------------------------------------------------------
// helpers
// ---------------------------------------------------------------------------
__device__ __forceinline__ uint32_t smem_u32(const void* p) {
    uint32_t a;
    asm("{ .reg .u64 t; cvta.to.shared.u64 t, %1; cvt.u32.u64 %0, t; }" : "=r"(a) : "l"(p));
    return a;
}
__device__ __forceinline__ void cp16(uint32_t dst, const void* src) {
    asm volatile("cp.async.cg.shared.global [%0], [%1], 16;" :: "r"(dst), "l"(src) : "memory");
}
#define CP_COMMIT() asm volatile("cp.async.commit_group;" ::: "memory")
#define CP_WAIT(N)  asm volatile("cp.async.wait_group %0;" :: "n"(N) : "memory")

#define LDSM_X4(d, addr) \
    asm volatile("ldmatrix.sync.aligned.m8n8.x4.shared.b16 {%0,%1,%2,%3}, [%4];" \
                 : "=r"((d)[0]), "=r"((d)[1]), "=r"((d)[2]), "=r"((d)[3]) : "r"(addr))

#define MMA16816(c, a, b0, b1) \
    asm volatile("mma.sync.aligned.m16n8k16.row.col.f32.bf16.bf16.f32 " \
                 "{%0,%1,%2,%3}, {%4,%5,%6,%7}, {%8,%9}, {%0,%1,%2,%3};" \
                 : "+f"((c)[0]), "+f"((c)[1]), "+f"((c)[2]), "+f"((c)[3]) \
                 : "r"((a)[0]), "r"((a)[1]), "r"((a)[2]), "r"((a)[3]), "r"(b0), "r"(b1))

// monotone float->uint order map, low 7 bits replaced by tile-local column
__device__ __forceinline__ uint32_t pack_key(float s, int col) {
    uint32_t u = __float_as_uint(s);
    u ^= ((uint32_t)((int32_t)u >> 31)) | 0x80000000u;
    return (u & 0xFFFFFF80u) | (uint32_t)col;
}

// ---------------------------------------------------------------------------
// Kernel 0: fused fp32->bf16 conversion + exact fp32 row norms. Warp per row.
// ---------------------------------------------------------------------------
__global__ void convsq_kernel(const float* __restrict__ zi, const float* __restrict__ zj) {
    int w = (blockIdx.x * blockDim.x + threadIdx.x) >> 5;
    int lane = threadIdx.x & 31;
    if (w >= BB) return;
    const float* p = (w < NS) ? zi + (size_t)w * DD : zj + (size_t)(w - NS) * DD;
    const float4* p4 = (const float4*)p;
    __nv_bfloat162* dst = (__nv_bfloat162*)(g_fb + (size_t)w * DD);
    float s = 0.f;
    #pragma unroll
    for (int k = lane; k < DD / 4; k += 32) {
        float4 v = p4[k];
        s += v.x * v.x + v.y * v.y + v.z * v.z + v.w * v.w;
        dst[2 * k]     = __floats2bfloat162_rn(v.x, v.y);
        dst[2 * k + 1] = __floats2bfloat162_rn(v.z, v.w);
    }
    #pragma unroll
    for (int o = 16; o; o >>= 1) s += __shfl_xor_sync(0xffffffffu, s, o);
    if (lane == 0) g_sq[w] = s;
}

// ---------------------------------------------------------------------------
// Kernel 2: bf16 mma.sync GEMM (128x128 tile) + fused per-(row,tile) top-12
// over PACKED 1-register keys. Diagonal element staged as 0xFFFFFFFF sentinel.
// ---------------------------------------------------------------------------
#define KT    16            // 512 / 32 k-tiles
#define SROW  40            // smem row stride in bf16 elems (80 B)
#define SBUF  (128 * SROW)  // elems per tile buffer (5120)
#define STG_STRIDE 132      // stage row stride in words
#define DYN_SMEM (128 * STG_STRIDE * 4)   // 67584 B (covers the 40960 B A/B bufs)

__global__ void __launch_bounds__(256, 2) gemm_select_kernel() {
    extern __shared__ __align__(16) char dsm[];
    __shared__ float s_sqn[128];

    __nv_bfloat16* As = (__nv_bfloat16*)dsm;             // [2][SBUF]
    __nv_bfloat16* Bs = (__nv_bfloat16*)(dsm + 20480);   // [2][SBUF]
    uint32_t* stg = (uint32_t*)dsm;                      // [128][132] packed keys

    const int tid = threadIdx.x;
    const int lane = tid & 31;
    const int wid = tid >> 5;
    const int wy = wid >> 2;
    const int wx = wid & 3;
    const int m0 = blockIdx.y << 7;
    const int n0 = blockIdx.x << 7;
    const int bj = blockIdx.x;

    if (tid < 128) s_sqn[tid] = g_sq[n0 + tid];

    const int lr = tid >> 1;
    const int lu = (tid & 1) * 16;
    const uint32_t sA = smem_u32(As);
    const uint32_t sB = smem_u32(Bs);
    const uint32_t sdoff = (uint32_t)(lr * SROW + lu) * 2;
    const __nv_bfloat16* gA = g_fb + (size_t)(m0 + lr) * DD + lu;
    const __nv_bfloat16* gB = g_fb + (size_t)(n0 + lr) * DD + lu;

    const int rowA = wy * 64 + (lane & 7) + ((lane >> 3) & 1) * 8;
    const int colA = (lane >> 4) * 8;
    const int rowB = wx * 32 + (lane & 7) + (lane >> 4) * 8;
    const int colB = ((lane >> 3) & 1) * 8;

    float acc[4][4][4];
    #pragma unroll
    for (int i = 0; i < 4; i++)
        #pragma unroll
        for (int j = 0; j < 4; j++)
            #pragma unroll
            for (int q = 0; q < 4; q++) acc[i][j][q] = 0.f;

    {
        cp16(sA + sdoff, gA); cp16(sA + sdoff + 16, gA + 8);
        cp16(sB + sdoff, gB); cp16(sB + sdoff + 16, gB + 8);
        CP_COMMIT();
    }

    for (int kt = 0; kt < KT; ++kt) {
        const int buf = kt & 1;
        if (kt + 1 < KT) {
            const uint32_t boff = (uint32_t)(buf ^ 1) * (SBUF * 2);
            const __nv_bfloat16* pa = gA + (kt + 1) * 32;
            const __nv_bfloat16* pb = gB + (kt + 1) * 32;
            cp16(sA + boff + sdoff, pa); cp16(sA + boff + sdoff + 16, pa + 8);
            cp16(sB + boff + sdoff, pb); cp16(sB + boff + sdoff + 16, pb + 8);
            CP_COMMIT();
            CP_WAIT(1);
        } else {
            CP_WAIT(0);
        }
        __syncthreads();

        const uint32_t ab = sA + (uint32_t)buf * (SBUF * 2);
        const uint32_t bb = sB + (uint32_t)buf * (SBUF * 2);
        #pragma unroll
        for (int ks = 0; ks < 2; ++ks) {
            uint32_t a[4][4], b[2][4];
            #pragma unroll
            for (int mi = 0; mi < 4; mi++)
                LDSM_X4(a[mi], ab + (uint32_t)((rowA + mi * 16) * SROW + ks * 16 + colA) * 2);
            #pragma unroll
            for (int ng = 0; ng < 2; ng++)
                LDSM_X4(b[ng], bb + (uint32_t)((rowB + ng * 16) * SROW + ks * 16 + colB) * 2);
            #pragma unroll
            for (int mi = 0; mi < 4; mi++)
                #pragma unroll
                for (int nb = 0; nb < 4; nb++)
                    MMA16816(acc[mi][nb], a[mi], b[nb >> 1][(nb & 1) * 2], b[nb >> 1][(nb & 1) * 2 + 1]);
        }
        __syncthreads();
    }
    // A/B smem dead; stage all packed keys so acc registers die here.

    {
        const int er = (lane >> 2);
        const int ec = wx * 32 + (lane & 3) * 2;
        #pragma unroll
        for (int mi = 0; mi < 4; mi++) {
            const int ra = wy * 64 + mi * 16 + er;
            const int rb = ra + 8;
            #pragma unroll
            for (int nb = 0; nb < 4; nb++) {
                const int cc = ec + nb * 8;
                const float sn0 = s_sqn[cc], sn1 = s_sqn[cc + 1];
                uint32_t k00 = pack_key(sn0 - 2.f * acc[mi][nb][0], cc);
                uint32_t k01 = pack_key(sn1 - 2.f * acc[mi][nb][1], cc + 1);
                uint32_t k10 = pack_key(sn0 - 2.f * acc[mi][nb][2], cc);
                uint32_t k11 = pack_key(sn1 - 2.f * acc[mi][nb][3], cc + 1);
                if (m0 + ra == n0 + cc)     k00 = 0xFFFFFFFFu;
                if (m0 + ra == n0 + cc + 1) k01 = 0xFFFFFFFFu;
                if (m0 + rb == n0 + cc)     k10 = 0xFFFFFFFFu;
                if (m0 + rb == n0 + cc + 1) k11 = 0xFFFFFFFFu;
                stg[ra * STG_STRIDE + cc]     = k00;
                stg[ra * STG_STRIDE + cc + 1] = k01;
                stg[rb * STG_STRIDE + cc]     = k10;
                stg[rb * STG_STRIDE + cc + 1] = k11;
            }
        }
    }
    __syncthreads();

    // ---- selection: quad per row, 2 row-passes; 1-register candidates ----
    const int g8 = lane >> 2;
    const int l4 = lane & 3;

    #pragma unroll 1
    for (int rp = 0; rp < 2; ++rp) {
        const int relrow = rp * 64 + wid * 8 + g8;     // 0..127
        uint32_t keys[KC];
        #pragma unroll
        for (int q = 0; q < KC; q++) keys[q] = 0xFFFFFFFFu;

        const uint32_t* srow = stg + relrow * STG_STRIDE;
        #pragma unroll
        for (int q = 0; q < 8; ++q) {
            uint4 k4 = *(const uint4*)(srow + q * 16 + l4 * 4);
            uint32_t kv[4] = {k4.x, k4.y, k4.z, k4.w};
            #pragma unroll
            for (int k = 0; k < 4; k++) {
                const uint32_t u = kv[k];
                if (u < keys[KC - 1]) {
                    keys[KC - 1] = u;
                    #pragma unroll
                    for (int s = KC - 1; s >= 1; s--) {
                        if (keys[s] < keys[s - 1]) {
                            uint32_t t = keys[s]; keys[s] = keys[s - 1]; keys[s - 1] = t;
                        }
                    }
                }
            }
        }

        // quad merge: 12 extract rounds; keys unique within tile -> unique owner
        uint32_t* crow = g_cand + ((size_t)(m0 + relrow) * NT_COL + bj) * KC;
        #pragma unroll
        for (int r = 0; r < KC; ++r) {
            uint32_t mv = keys[0];
            #pragma unroll
            for (int o = 1; o <= 2; o <<= 1) {
                uint32_t ov = __shfl_xor_sync(0xffffffffu, mv, o);
                mv = (ov < mv) ? ov : mv;
            }
            if (keys[0] == mv) {   // unique owner pops its head
                #pragma unroll
                for (int s = 0; s < KC - 1; s++) keys[s] = keys[s + 1];
                keys[KC - 1] = 0xFFFFFFFFu;
            }
            if (l4 == 0) crow[r] = mv;
        }
    }
}

// ---------------------------------------------------------------------------
// Kernel 3: merge 32x12 packed per-tile candidates -> approx top-12 -> exact
// fp32 rescore -> exact top-10 -> weights, masked prob-dots. Warp per row.
// ---------------------------------------------------------------------------
__global__ void merge_loss_kernel(const float* __restrict__ zi,
                                  const float* __restrict__ zj,
                                  const float* __restrict__ zip,
                                  const float* __restrict__ zjp,
                                  const int* __restrict__ label) {
    int w = (blockIdx.x * blockDim.x + threadIdx.x) >> 5;
    int lane = threadIdx.x & 31;
    if (w >= BB) return;
    const int i = w;
    const uint32_t* crow = g_cand + (size_t)i * (NT_COL * KC);

    // per-lane sorted top-12 over its 12 assigned candidates
    // compare by (key, gcol) pair: keys may collide across tiles, gcol unique
    uint32_t v[KC]; int c[KC];
    #pragma unroll
    for (int q = 0; q < KC; q++) { v[q] = 0xFFFFFFFFu; c[q] = 0x7fffffff; }
    #pragma unroll
    for (int t = 0; t < KC; ++t) {
        const int e = t * 32 + lane;          // 0..383
        const uint32_t k = crow[e];
        const int tile = e / KC;
        const int gcol = tile * 128 + (int)(k & 127u);
        if (k < v[KC - 1] || (k == v[KC - 1] && gcol < c[KC - 1])) {
            v[KC - 1] = k; c[KC - 1] = gcol;
            #pragma unroll
            for (int q = KC - 1; q >= 1; q--) {
                if (v[q] < v[q - 1] || (v[q] == v[q - 1] && c[q] < c[q - 1])) {
                    uint32_t tv = v[q]; v[q] = v[q - 1]; v[q - 1] = tv;
                    int tc = c[q]; c[q] = c[q - 1]; c[q - 1] = tc;
                }
            }
        }
    }

    // full-warp merge: 12 rounds of argmin-extract
    int rc[KC];
    #pragma unroll
    for (int r = 0; r < KC; r++) {
        uint32_t mv = v[0]; int mc = c[0];
        #pragma unroll
        for (int o = 16; o; o >>= 1) {
            uint32_t ov = __shfl_down_sync(0xffffffffu, mv, o);
            int oc = __shfl_down_sync(0xffffffffu, mc, o);
            if (ov < mv || (ov == mv && oc < mc)) { mv = ov; mc = oc; }
        }
        mc = __shfl_sync(0xffffffffu, mc, 0);
        rc[r] = mc;
        if (c[0] == mc) {
            #pragma unroll
            for (int q = 0; q < KC - 1; q++) { v[q] = v[q + 1]; c[q] = c[q + 1]; }
            v[KC - 1] = 0xFFFFFFFFu; c[KC - 1] = 0x7fffffff;
        }
    }

    // exact fp32 rescore of the 12 candidates
    const float* fip = (i < NS) ? zi + (size_t)i * DD : zj + (size_t)(i - NS) * DD;
    float4 fi[4];
    #pragma unroll
    for (int q = 0; q < 4; q++) fi[q] = ((const float4*)fip)[lane + 32 * q];
    const float sqi = g_sq[i];

    float rd[KC];
    #pragma unroll
    for (int r = 0; r < KC; r++) {
        int j = rc[r];
        const float* fjp = (j < NS) ? zi + (size_t)j * DD : zj + (size_t)(j - NS) * DD;
        float s = 0.f;
        #pragma unroll
        for (int q = 0; q < 4; q++) {
            float4 fj = ((const float4*)fjp)[lane + 32 * q];
            s += fi[q].x * fj.x + fi[q].y * fj.y + fi[q].z * fj.z + fi[q].w * fj.w;
        }
        #pragma unroll
        for (int o = 16; o; o >>= 1) s += __shfl_xor_sync(0xffffffffu, s, o);
        rd[r] = sqi + g_sq[j] - 2.f * s;           // exact d2 (all lanes agree)
    }

    // per-lane redundant sort of 12 (ascending d2, index tiebreak)
    #pragma unroll
    for (int a = 1; a < KC; a++) {
        float dv = rd[a]; int ci = rc[a];
        int b = a;
        while (b > 0 && (rd[b - 1] > dv || (rd[b - 1] == dv && rc[b - 1] > ci))) {
            rd[b] = rd[b - 1]; rc[b] = rc[b - 1]; --b;
        }
        rd[b] = dv; rc[b] = ci;
    }

    // weights + masked prob-dots over exact top-10
    float radius = sqrtf(fmaxf(rd[0], 0.f));
    const float* prow = (i < NS) ? zip + (size_t)i * CC : zjp + (size_t)(i - NS) * CC;
    float4 myp = ((const float4*)prow)[lane];
    const int im = i & (NS - 1);
    const int li = label[im];
    float rowsum = 0.f;
    #pragma unroll
    for (int r = 0; r < 10; r++) {
        int j = rc[r];
        int jm = j & (NS - 1);
        if (li == label[jm] && li != -1 && im != jm) {
            const float* pr = (j < NS) ? zip + (size_t)j * CC : zjp + (size_t)(j - NS) * CC;
            float4 q4 = ((const float4*)pr)[lane];
            float part = myp.x * q4.x + myp.y * q4.y + myp.z * q4.z + myp.w * q4.w;
            #pragma unroll
            for (int o = 16; o; o >>= 1) part += __shfl_xor_sync(0xffffffffu, part, o);
            float pd = sqrtf(fmaxf(rd[r], 0.f));
            float ww = 1.f - fminf(fmaxf((pd - radius) / radius, 0.f), 1.f);
            rowsum += ww * part;
        }
    }
    if (lane == 0) g_part[i] = rowsum;
}

// ---------------------------------------------------------------------------
// Kernel 4: deterministic tree reduction -> scalar mean
// ---------------------------------------------------------------------------
__global__ void reduce_kernel(float* __restrict__ out) {
    __shared__ float s[1024];
    int t = threadIdx.x;
    float a = g_part[t] + g_part[t + 1024] + g_part[t + 2048] + g_part[t + 3072];
    s[t] = a;
    __syncthreads();
    for (int o = 512; o; o >>= 1) {
        if (t < o) s[t] += s[t + o];
        __syncthreads();
    }
    if (t == 0) out[0] = s[0] * (1.0f / ((float)BB * (float)BB));
}

// ---------------------------------------------------------------------------
extern "C" void kernel_launch(void* const* d_in, const int* in_sizes, int n_in,
                              void* d_out, int out_size) {
    const float* z_i = (const float*)d_in[0];
    const float* z_j = (const float*)d_in[1];
    const float* z_i_prob = (const float*)d_in[2];
    const float* z_j_prob = (const float*)d_in[3];
    const int* pseudo_label = (const int*)d_in[4];
    float* out = (float*)d_out;

    cudaFuncSetAttribute(gemm_select_kernel,
                         cudaFuncAttributeMaxDynamicSharedMemorySize, DYN_SMEM);

    convsq_kernel<<<BB / 8, 256>>>(z_i, z_j);
    gemm_select_kernel<<<dim3(32, 32), 256, DYN_SMEM>>>();
    merge_loss_kernel<<<BB / 8, 256>>>(z_i, z_j, z_i_prob, z_j_prob, pseudo_label);
    reduce_kernel<<<1, 1024>>>(out);
}

// round 9
// speedup vs baseline: 3.1076x; 1.1899x over previous
#include <cuda_runtime.h>
#include <cuda_bf16.h>
#include <math.h>
#include <float.h>
#include <stdint.h>

// Problem constants
#define NS 2048        // n
#define BB 4096        // 2n
#define DD 512         // feature dim
#define CC 128         // num classes
#define KC 12          // candidates per (row,tile) and final candidate count
#define NT_COL 32      // 4096/128 column tiles
#define NTILES 528     // upper-triangular 32x32 tile count

// Scratch (allocation-free rule: __device__ globals)
__device__ float g_sq[BB];                                          // exact fp32 row squared norms
__device__ float g_part[BB];                                        // per-row partial sums
__device__ int g_ctr;                                               // last-block counter
__device__ __align__(16) __nv_bfloat16 g_fb[(size_t)BB * DD];       // 4 MB bf16 feats
__device__ __align__(16) uint32_t g_cand[(size_t)BB * NT_COL * KC]; // 6.3 MB packed keys

// ---------------------------------------------------------------------------
// helpers
// ---------------------------------------------------------------------------
__device__ __forceinline__ uint32_t smem_u32(const void* p) {
    uint32_t a;
    asm("{ .reg .u64 t; cvta.to.shared.u64 t, %1; cvt.u32.u64 %0, t; }" : "=r"(a) : "l"(p));
    return a;
}
__device__ __forceinline__ void cp16(uint32_t dst, const void* src) {
    asm volatile("cp.async.cg.shared.global [%0], [%1], 16;" :: "r"(dst), "l"(src) : "memory");
}
#define CP_COMMIT() asm volatile("cp.async.commit_group;" ::: "memory")
#define CP_WAIT(N)  asm volatile("cp.async.wait_group %0;" :: "n"(N) : "memory")

#define LDSM_X4(d, addr) \
    asm volatile("ldmatrix.sync.aligned.m8n8.x4.shared.b16 {%0,%1,%2,%3}, [%4];" \
                 : "=r"((d)[0]), "=r"((d)[1]), "=r"((d)[2]), "=r"((d)[3]) : "r"(addr))

#define MMA16816(c, a, b0, b1) \
    asm volatile("mma.sync.aligned.m16n8k16.row.col.f32.bf16.bf16.f32 " \
                 "{%0,%1,%2,%3}, {%4,%5,%6,%7}, {%8,%9}, {%0,%1,%2,%3};" \
                 : "+f"((c)[0]), "+f"((c)[1]), "+f"((c)[2]), "+f"((c)[3]) \
                 : "r"((a)[0]), "r"((a)[1]), "r"((a)[2]), "r"((a)[3]), "r"(b0), "r"(b1))

// monotone float->uint order map, low 7 bits replaced by tile-local index
__device__ __forceinline__ uint32_t pack_key(float s, int idx) {
    uint32_t u = __float_as_uint(s);
    u ^= ((uint32_t)((int32_t)u >> 31)) | 0x80000000u;
    return (u & 0xFFFFFF80u) | (uint32_t)idx;
}

// ---------------------------------------------------------------------------
// Kernel 0: fused fp32->bf16 conversion + exact fp32 row norms. Warp per row.
// Also resets the last-block counter (graph-replay safe).
// ---------------------------------------------------------------------------
__global__ void convsq_kernel(const float* __restrict__ zi, const float* __restrict__ zj) {
    if (blockIdx.x == 0 && threadIdx.x == 0) g_ctr = 0;
    int w = (blockIdx.x * blockDim.x + threadIdx.x) >> 5;
    int lane = threadIdx.x & 31;
    if (w >= BB) return;
    const float* p = (w < NS) ? zi + (size_t)w * DD : zj + (size_t)(w - NS) * DD;
    const float4* p4 = (const float4*)p;
    __nv_bfloat162* dst = (__nv_bfloat162*)(g_fb + (size_t)w * DD);
    float s = 0.f;
    #pragma unroll
    for (int k = lane; k < DD / 4; k += 32) {
        float4 v = p4[k];
        s += v.x * v.x + v.y * v.y + v.z * v.z + v.w * v.w;
        dst[2 * k]     = __floats2bfloat162_rn(v.x, v.y);
        dst[2 * k + 1] = __floats2bfloat162_rn(v.z, v.w);
    }
    #pragma unroll
    for (int o = 16; o; o >>= 1) s += __shfl_xor_sync(0xffffffffu, s, o);
    if (lane == 0) g_sq[w] = s;
}

// ---------------------------------------------------------------------------
// Kernel 2: SYMMETRIC bf16 mma.sync GEMM — only 528 upper-tri 128x128 tiles.
// Epilogue stages raw dot to smem, then runs BOTH a row-pass (ranks cols for
// m-rows) and, for off-diagonal tiles, a col-pass (ranks rows for n-cols).
// ---------------------------------------------------------------------------
#define KT    16            // 512 / 32 k-tiles
#define SROW  40            // smem row stride in bf16 elems (80 B)
#define SBUF  (128 * SROW)  // elems per tile buffer (5120)
#define STG_STRIDE 132      // stage row stride in words
#define DYN_SMEM (128 * STG_STRIDE * 4)   // 67584 B (covers the 40960 B A/B bufs)

__global__ void __launch_bounds__(256, 2) gemm_select_kernel() {
    extern __shared__ __align__(16) char dsm[];
    __shared__ float s_sqm[128], s_sqn[128];

    __nv_bfloat16* As = (__nv_bfloat16*)dsm;             // [2][SBUF]
    __nv_bfloat16* Bs = (__nv_bfloat16*)(dsm + 20480);   // [2][SBUF]
    float* stg = (float*)dsm;                            // [128][132] raw dots

    const int tid = threadIdx.x;
    const int lane = tid & 31;
    const int wid = tid >> 5;
    const int wy = wid >> 2;
    const int wx = wid & 3;

    // upper-tri tile map: blockIdx.x -> (bi, bj), bj >= bi
    int t = blockIdx.x;
    int bi = 0;
    while (t >= NT_COL - bi) { t -= NT_COL - bi; ++bi; }
    const int bj = bi + t;
    const int m0 = bi << 7;
    const int n0 = bj << 7;
    const bool diag = (bi == bj);

    if (tid < 128) { s_sqm[tid] = g_sq[m0 + tid]; s_sqn[tid] = g_sq[n0 + tid]; }

    const int lr = tid >> 1;
    const int lu = (tid & 1) * 16;
    const uint32_t sA = smem_u32(As);
    const uint32_t sB = smem_u32(Bs);
    const uint32_t sdoff = (uint32_t)(lr * SROW + lu) * 2;
    const __nv_bfloat16* gA = g_fb + (size_t)(m0 + lr) * DD + lu;
    const __nv_bfloat16* gB = g_fb + (size_t)(n0 + lr) * DD + lu;

    const int rowA = wy * 64 + (lane & 7) + ((lane >> 3) & 1) * 8;
    const int colA = (lane >> 4) * 8;
    const int rowB = wx * 32 + (lane & 7) + (lane >> 4) * 8;
    const int colB = ((lane >> 3) & 1) * 8;

    float acc[4][4][4];
    #pragma unroll
    for (int i = 0; i < 4; i++)
        #pragma unroll
        for (int j = 0; j < 4; j++)
            #pragma unroll
            for (int q = 0; q < 4; q++) acc[i][j][q] = 0.f;

    {
        cp16(sA + sdoff, gA); cp16(sA + sdoff + 16, gA + 8);
        cp16(sB + sdoff, gB); cp16(sB + sdoff + 16, gB + 8);
        CP_COMMIT();
    }

    for (int kt = 0; kt < KT; ++kt) {
        const int buf = kt & 1;
        if (kt + 1 < KT) {
            const uint32_t boff = (uint32_t)(buf ^ 1) * (SBUF * 2);
            const __nv_bfloat16* pa = gA + (kt + 1) * 32;
            const __nv_bfloat16* pb = gB + (kt + 1) * 32;
            cp16(sA + boff + sdoff, pa); cp16(sA + boff + sdoff + 16, pa + 8);
            cp16(sB + boff + sdoff, pb); cp16(sB + boff + sdoff + 16, pb + 8);
            CP_COMMIT();
            CP_WAIT(1);
        } else {
            CP_WAIT(0);
        }
        __syncthreads();

        const uint32_t ab = sA + (uint32_t)buf * (SBUF * 2);
        const uint32_t bb = sB + (uint32_t)buf * (SBUF * 2);
        #pragma unroll
        for (int ks = 0; ks < 2; ++ks) {
            uint32_t a[4][4], b[2][4];
            #pragma unroll
            for (int mi = 0; mi < 4; mi++)
                LDSM_X4(a[mi], ab + (uint32_t)((rowA + mi * 16) * SROW + ks * 16 + colA) * 2);
            #pragma unroll
            for (int ng = 0; ng < 2; ng++)
                LDSM_X4(b[ng], bb + (uint32_t)((rowB + ng * 16) * SROW + ks * 16 + colB) * 2);
            #pragma unroll
            for (int mi = 0; mi < 4; mi++)
                #pragma unroll
                for (int nb = 0; nb < 4; nb++)
                    MMA16816(acc[mi][nb], a[mi], b[nb >> 1][(nb & 1) * 2], b[nb >> 1][(nb & 1) * 2 + 1]);
        }
        __syncthreads();
    }
    // A/B smem dead; stage raw dot values so acc registers die here.

    {
        const int er = (lane >> 2);
        const int ec = wx * 32 + (lane & 3) * 2;
        #pragma unroll
        for (int mi = 0; mi < 4; mi++) {
            const int ra = wy * 64 + mi * 16 + er;
            const int rb = ra + 8;
            #pragma unroll
            for (int nb = 0; nb < 4; nb++) {
                const int cc = ec + nb * 8;
                stg[ra * STG_STRIDE + cc]     = acc[mi][nb][0];
                stg[ra * STG_STRIDE + cc + 1] = acc[mi][nb][1];
                stg[rb * STG_STRIDE + cc]     = acc[mi][nb][2];
                stg[rb * STG_STRIDE + cc + 1] = acc[mi][nb][3];
            }
        }
    }
    __syncthreads();

    const int g8 = lane >> 2;
    const int l4 = lane & 3;

    // ---- ROW PASS: rank cols (block bj) for each m-row ----
    #pragma unroll 1
    for (int rp = 0; rp < 2; ++rp) {
        const int relrow = rp * 64 + wid * 8 + g8;     // 0..127
        uint32_t keys[KC];
        #pragma unroll
        for (int q = 0; q < KC; q++) keys[q] = 0xFFFFFFFFu;

        const float* srow = stg + relrow * STG_STRIDE;
        #pragma unroll
        for (int q = 0; q < 8; ++q) {
            float4 d4 = *(const float4*)(srow + q * 16 + l4 * 4);
            const int cb = q * 16 + l4 * 4;
            float dv[4] = {d4.x, d4.y, d4.z, d4.w};
            #pragma unroll
            for (int k = 0; k < 4; k++) {
                const int c = cb + k;
                uint32_t u = pack_key(fmaf(-2.f, dv[k], s_sqn[c]), c);
                if (diag && c == relrow) u = 0xFFFFFFFFu;
                if (u < keys[KC - 1]) {
                    keys[KC - 1] = u;
                    #pragma unroll
                    for (int s = KC - 1; s >= 1; s--) {
                        if (keys[s] < keys[s - 1]) {
                            uint32_t tt = keys[s]; keys[s] = keys[s - 1]; keys[s - 1] = tt;
                        }
                    }
                }
            }
        }

        uint32_t* crow = g_cand + ((size_t)(m0 + relrow) * NT_COL + bj) * KC;
        #pragma unroll
        for (int r = 0; r < KC; ++r) {
            uint32_t mv = keys[0];
            #pragma unroll
            for (int o = 1; o <= 2; o <<= 1) {
                uint32_t ov = __shfl_xor_sync(0xffffffffu, mv, o);
                mv = (ov < mv) ? ov : mv;
            }
            if (keys[0] == mv) {
                #pragma unroll
                for (int s = 0; s < KC - 1; s++) keys[s] = keys[s + 1];
                keys[KC - 1] = 0xFFFFFFFFu;
            }
            if (l4 == 0) crow[r] = mv;
        }
    }

    // ---- COL PASS (off-diagonal only): rank rows (block bi) for each n-col ----
    if (!diag) {
        #pragma unroll 1
        for (int rp = 0; rp < 2; ++rp) {
            const int relcol = rp * 64 + wid * 8 + g8;   // 0..127
            uint32_t keys[KC];
            #pragma unroll
            for (int q = 0; q < KC; q++) keys[q] = 0xFFFFFFFFu;

            #pragma unroll 4
            for (int it = 0; it < 32; ++it) {
                const int r = l4 + 4 * it;
                const float dot = stg[r * STG_STRIDE + relcol];
                uint32_t u = pack_key(fmaf(-2.f, dot, s_sqm[r]), r);
                if (u < keys[KC - 1]) {
                    keys[KC - 1] = u;
                    #pragma unroll
                    for (int s = KC - 1; s >= 1; s--) {
                        if (keys[s] < keys[s - 1]) {
                            uint32_t tt = keys[s]; keys[s] = keys[s - 1]; keys[s - 1] = tt;
                        }
                    }
                }
            }

            uint32_t* crow = g_cand + ((size_t)(n0 + relcol) * NT_COL + bi) * KC;
            #pragma unroll
            for (int r = 0; r < KC; ++r) {
                uint32_t mv = keys[0];
                #pragma unroll
                for (int o = 1; o <= 2; o <<= 1) {
                    uint32_t ov = __shfl_xor_sync(0xffffffffu, mv, o);
                    mv = (ov < mv) ? ov : mv;
                }
                if (keys[0] == mv) {
                    #pragma unroll
                    for (int s = 0; s < KC - 1; s++) keys[s] = keys[s + 1];
                    keys[KC - 1] = 0xFFFFFFFFu;
                }
                if (l4 == 0) crow[r] = mv;
            }
        }
    }
}

// ---------------------------------------------------------------------------
// Kernel 3: merge 32x12 packed per-tile candidates -> approx top-12 -> exact
// fp32 rescore -> exact top-10 -> weights, masked prob-dots. Warp per row.
// Last-arriving block performs the deterministic final reduction.
// ---------------------------------------------------------------------------
__global__ void merge_loss_kernel(const float* __restrict__ zi,
                                  const float* __restrict__ zj,
                                  const float* __restrict__ zip,
                                  const float* __restrict__ zjp,
                                  const int* __restrict__ label,
                                  float* __restrict__ out) {
    int w = (blockIdx.x * blockDim.x + threadIdx.x) >> 5;
    int lane = threadIdx.x & 31;
    const int i = w;
    const uint32_t* crow = g_cand + (size_t)i * (NT_COL * KC);

    // per-lane sorted top-12 over its 12 assigned candidates
    uint32_t v[KC]; int c[KC];
    #pragma unroll
    for (int q = 0; q < KC; q++) { v[q] = 0xFFFFFFFFu; c[q] = 0x7fffffff; }
    #pragma unroll
    for (int t = 0; t < KC; ++t) {
        const int e = t * 32 + lane;          // 0..383
        const uint32_t k = crow[e];
        const int tile = e / KC;
        const int gcol = tile * 128 + (int)(k & 127u);
        if (k < v[KC - 1] || (k == v[KC - 1] && gcol < c[KC - 1])) {
            v[KC - 1] = k; c[KC - 1] = gcol;
            #pragma unroll
            for (int q = KC - 1; q >= 1; q--) {
                if (v[q] < v[q - 1] || (v[q] == v[q - 1] && c[q] < c[q - 1])) {
                    uint32_t tv = v[q]; v[q] = v[q - 1]; v[q - 1] = tv;
                    int tc = c[q]; c[q] = c[q - 1]; c[q - 1] = tc;
                }
            }
        }
    }

    // full-warp merge: 12 rounds of argmin-extract
    int rc[KC];
    #pragma unroll
    for (int r = 0; r < KC; r++) {
        uint32_t mv = v[0]; int mc = c[0];
        #pragma unroll
        for (int o = 16; o; o >>= 1) {
            uint32_t ov = __shfl_down_sync(0xffffffffu, mv, o);
            int oc = __shfl_down_sync(0xffffffffu, mc, o);
            if (ov < mv || (ov == mv && oc < mc)) { mv = ov; mc = oc; }
        }
        mc = __shfl_sync(0xffffffffu, mc, 0);
        rc[r] = mc;
        if (c[0] == mc) {
            #pragma unroll
            for (int q = 0; q < KC - 1; q++) { v[q] = v[q + 1]; c[q] = c[q + 1]; }
            v[KC - 1] = 0xFFFFFFFFu; c[KC - 1] = 0x7fffffff;
        }
    }

    // exact fp32 rescore of the 12 candidates
    const float* fip = (i < NS) ? zi + (size_t)i * DD : zj + (size_t)(i - NS) * DD;
    float4 fi[4];
    #pragma unroll
    for (int q = 0; q < 4; q++) fi[q] = ((const float4*)fip)[lane + 32 * q];
    const float sqi = g_sq[i];

    float rd[KC];
    #pragma unroll
    for (int r = 0; r < KC; r++) {
        int j = rc[r];
        const float* fjp = (j < NS) ? zi + (size_t)j * DD : zj + (size_t)(j - NS) * DD;
        float s = 0.f;
        #pragma unroll
        for (int q = 0; q < 4; q++) {
            float4 fj = ((const float4*)fjp)[lane + 32 * q];
            s += fi[q].x * fj.x + fi[q].y * fj.y + fi[q].z * fj.z + fi[q].w * fj.w;
        }
        #pragma unroll
        for (int o = 16; o; o >>= 1) s += __shfl_xor_sync(0xffffffffu, s, o);
        rd[r] = sqi + g_sq[j] - 2.f * s;           // exact d2 (all lanes agree)
    }

    // per-lane redundant sort of 12 (ascending d2, index tiebreak)
    #pragma unroll
    for (int a = 1; a < KC; a++) {
        float dv = rd[a]; int ci = rc[a];
        int b = a;
        while (b > 0 && (rd[b - 1] > dv || (rd[b - 1] == dv && rc[b - 1] > ci))) {
            rd[b] = rd[b - 1]; rc[b] = rc[b - 1]; --b;
        }
        rd[b] = dv; rc[b] = ci;
    }

    // weights + masked prob-dots over exact top-10
    float radius = sqrtf(fmaxf(rd[0], 0.f));
    const float* prow = (i < NS) ? zip + (size_t)i * CC : zjp + (size_t)(i - NS) * CC;
    float4 myp = ((const float4*)prow)[lane];
    const int im = i & (NS - 1);
    const int li = label[im];
    float rowsum = 0.f;
    #pragma unroll
    for (int r = 0; r < 10; r++) {
        int j = rc[r];
        int jm = j & (NS - 1);
        if (li == label[jm] && li != -1 && im != jm) {
            const float* pr = (j < NS) ? zip + (size_t)j * CC : zjp + (size_t)(j - NS) * CC;
            float4 q4 = ((const float4*)pr)[lane];
            float part = myp.x * q4.x + myp.y * q4.y + myp.z * q4.z + myp.w * q4.w;
            #pragma unroll
            for (int o = 16; o; o >>= 1) part += __shfl_xor_sync(0xffffffffu, part, o);
            float pd = sqrtf(fmaxf(rd[r], 0.f));
            float ww = 1.f - fminf(fmaxf((pd - radius) / radius, 0.f), 1.f);
            rowsum += ww * part;
        }
    }
    if (lane == 0) g_part[i] = rowsum;

    // ---- last-block deterministic reduction ----
    __shared__ int s_last;
    __shared__ float s_red[256];
    __threadfence();
    __syncthreads();
    if (threadIdx.x == 0) s_last = (atomicAdd(&g_ctr, 1) == gridDim.x - 1) ? 1 : 0;
    __syncthreads();
    if (s_last) {
        int tdx = threadIdx.x;
        float a = 0.f;
        #pragma unroll
        for (int q = 0; q < 16; q++) a += g_part[tdx + 256 * q];
        s_red[tdx] = a;
        __syncthreads();
        for (int o = 128; o; o >>= 1) {
            if (tdx < o) s_red[tdx] += s_red[tdx + o];
            __syncthreads();
        }
        if (tdx == 0) out[0] = s_red[0] * (1.0f / ((float)BB * (float)BB));
    }
}

// ---------------------------------------------------------------------------
extern "C" void kernel_launch(void* const* d_in, const int* in_sizes, int n_in,
                              void* d_out, int out_size) {
    const float* z_i = (const float*)d_in[0];
    const float* z_j = (const float*)d_in[1];
    const float* z_i_prob = (const float*)d_in[2];
    const float* z_j_prob = (const float*)d_in[3];
    const int* pseudo_label = (const int*)d_in[4];
    float* out = (float*)d_out;

    cudaFuncSetAttribute(gemm_select_kernel,
                         cudaFuncAttributeMaxDynamicSharedMemorySize, DYN_SMEM);

    convsq_kernel<<<BB / 8, 256>>>(z_i, z_j);
    gemm_select_kernel<<<NTILES, 256, DYN_SMEM>>>();
    merge_loss_kernel<<<BB / 8, 256>>>(z_i, z_j, z_i_prob, z_j_prob, pseudo_label, out);
}